// round 14
// baseline (speedup 1.0000x reference)
#include <cuda_runtime.h>
#include <cuda_fp16.h>
#include <cstdint>

#define NN_ 8192
#define EE_ 524288
#define HH_ 128
#define IND_ 32
#define NCC_ 16

// Device scratch (static, no allocations)
__device__ __align__(16) float g_cx[NN_ * HH_];
__device__ __align__(16) float g_agg[NN_ * HH_];
__device__ __align__(16) float g_z[NN_ * HH_];
__device__ __align__(16) __half g_zh[NN_ * HH_];
__device__ __align__(16) __half g_zl[NN_ * HH_];
__device__ __align__(16) __half g_W2h[HH_ * HH_];  // eeW2^T [n][k] hi
__device__ __align__(16) __half g_W2l[HH_ * HH_];  // eeW2^T [n][k] lo
__device__ int g_is64;

// ---------------------------------------------------------------------------
__device__ __forceinline__ void red_add_v2(float* addr, float x, float y) {
    asm volatile("red.global.add.v2.f32 [%0], {%1,%2};"
                 :: "l"(addr), "f"(x), "f"(y) : "memory");
}
__device__ __forceinline__ uint32_t smem_u32(const void* p) {
    return (uint32_t)__cvta_generic_to_shared(p);
}
__device__ __forceinline__ void ldmx4(uint32_t r[4], uint32_t addr) {
    asm volatile("ldmatrix.sync.aligned.m8n8.x4.shared.b16 {%0,%1,%2,%3}, [%4];"
                 : "=r"(r[0]), "=r"(r[1]), "=r"(r[2]), "=r"(r[3]) : "r"(addr));
}
__device__ __forceinline__ void mma16816(float c[4], const uint32_t a[4],
                                         uint32_t b0, uint32_t b1) {
    asm volatile("mma.sync.aligned.m16n8k16.row.col.f32.f16.f16.f32 "
                 "{%0,%1,%2,%3}, {%4,%5,%6,%7}, {%8,%9}, {%0,%1,%2,%3};"
                 : "+f"(c[0]), "+f"(c[1]), "+f"(c[2]), "+f"(c[3])
                 : "r"(a[0]), "r"(a[1]), "r"(a[2]), "r"(a[3]), "r"(b0), "r"(b1));
}

#define LDAH_ 136
// 3-term split MMA, 8 warps as 2(m)x4(n), warp tile 64x32.
// SOFTWARE-PIPELINED: A fragments double-buffered in regs; the ldmatrix for
// the next mt (or next ks, mt0) issues BEFORE the current mt's 12 MMAs.
__device__ __forceinline__ void mma_tile_3x(
    float acc[4][4][4], uint32_t sAh, uint32_t sAl, uint32_t sBh, uint32_t sBl,
    int wm, int wn, int lane)
{
    int lrow = lane & 15;
    int lcol = (lane >> 4) * 8;
    uint32_t ah[2][4], al[2][4];
    {   // prologue: A(ks=0, mt=0)
        uint32_t off = (uint32_t)(((wm + lrow) * LDAH_ + lcol) * 2);
        ldmx4(ah[0], sAh + off);
        ldmx4(al[0], sAl + off);
    }
#pragma unroll 1
    for (int ks = 0; ks < 8; ++ks) {
        int kk = ks * 16;
        uint32_t bh[2][4], bl[2][4];
#pragma unroll
        for (int bt = 0; bt < 2; ++bt) {
            uint32_t off = (uint32_t)(((wn + bt * 16 + lrow) * LDAH_ + kk + lcol) * 2);
            ldmx4(bh[bt], sBh + off);
            ldmx4(bl[bt], sBl + off);
        }
#pragma unroll
        for (int mt = 0; mt < 4; ++mt) {
            int cur = mt & 1, nxt = cur ^ 1;
            // prefetch next A fragments
            if (mt < 3) {
                uint32_t off = (uint32_t)(((wm + (mt + 1) * 16 + lrow) * LDAH_ + kk + lcol) * 2);
                ldmx4(ah[nxt], sAh + off);
                ldmx4(al[nxt], sAl + off);
            } else if (ks < 7) {
                uint32_t off = (uint32_t)(((wm + lrow) * LDAH_ + kk + 16 + lcol) * 2);
                ldmx4(ah[nxt], sAh + off);
                ldmx4(al[nxt], sAl + off);
            }
            // 12 MMAs (term-major) on current fragments
#pragma unroll
            for (int nt = 0; nt < 4; ++nt) {
                int bt = nt >> 1, sel = nt & 1;
                mma16816(acc[mt][nt], ah[cur], bh[bt][sel], bh[bt][sel + 2]);
            }
#pragma unroll
            for (int nt = 0; nt < 4; ++nt) {
                int bt = nt >> 1, sel = nt & 1;
                mma16816(acc[mt][nt], ah[cur], bl[bt][sel], bl[bt][sel + 2]);
            }
#pragma unroll
            for (int nt = 0; nt < 4; ++nt) {
                int bt = nt >> 1, sel = nt & 1;
                mma16816(acc[mt][nt], al[cur], bh[bt][sel], bh[bt][sel + 2]);
            }
        }
    }
}

__device__ __forceinline__ void stage_acc(float* shAcc, float acc[4][4][4],
                                          int wm, int wn, int lane)
{
#pragma unroll
    for (int mt = 0; mt < 4; ++mt)
#pragma unroll
        for (int nt = 0; nt < 4; ++nt) {
            int r = wm + mt * 16 + (lane >> 2);
            int c = wn + nt * 8 + (lane & 3) * 2;
            shAcc[r * 132 + c] = acc[mt][nt][0];
            shAcc[r * 132 + c + 1] = acc[mt][nt][1];
            shAcc[(r + 8) * 132 + c] = acc[mt][nt][2];
            shAcc[(r + 8) * 132 + c + 1] = acc[mt][nt][3];
        }
}

// ---------------------------------------------------------------------------
__global__ void k_prep(const int* __restrict__ ei32) {
    if (blockIdx.x == 0 && threadIdx.x == 0) {
        int all0 = 1;
        for (int i = 0; i < 64; ++i)
            if (ei32[2 * i + 1] != 0) { all0 = 0; break; }
        g_is64 = all0;
    }
    int idx = blockIdx.x * blockDim.x + threadIdx.x;
    float4* p = reinterpret_cast<float4*>(g_agg);
    int n4 = NN_ * HH_ / 4;
    for (int i = idx; i < n4; i += gridDim.x * blockDim.x)
        p[i] = make_float4(0.f, 0.f, 0.f, 0.f);
}

__global__ void k_split_w2(const float* __restrict__ W2) {
    int idx = blockIdx.x * 256 + threadIdx.x;
    int k = idx >> 7, n = idx & 127;
    float v = W2[k * 128 + n];
    __half h = __float2half_rn(v);
    g_W2h[n * 128 + k] = h;
    g_W2l[n * 128 + k] = __float2half_rn(v - __half2float(h));
}

// ---------------------------------------------------------------------------
// K_node: 256 CTAs x 32 rows
__global__ void __launch_bounds__(256)
k_node_enc(const float* __restrict__ x,
           const float* __restrict__ W1, const float* __restrict__ b1,
           const float* __restrict__ a_p,
           const float* __restrict__ W2, const float* __restrict__ b2)
{
    __shared__ float shA[32 * 129];
    __shared__ float shB[32 * 128];
    __shared__ float shX[32 * 33];
    int tid = threadIdx.x;
    int tx = tid & 15, ty = tid >> 4;
    int base = blockIdx.x * 32;

    for (int idx = tid; idx < 32 * 32; idx += 256) {
        int r = idx >> 5, k = idx & 31;
        shX[r * 33 + k] = x[(base + r) * IND_ + k];
    }
    for (int idx = tid; idx < 32 * 128; idx += 256) shB[idx] = W1[idx];
    __syncthreads();

    float acc[2][8];
#pragma unroll
    for (int i = 0; i < 2; ++i)
#pragma unroll
        for (int j = 0; j < 8; ++j) acc[i][j] = 0.f;

#pragma unroll 4
    for (int k = 0; k < 32; ++k) {
        float a0 = shX[(ty * 2 + 0) * 33 + k];
        float a1 = shX[(ty * 2 + 1) * 33 + k];
        float4 b0 = *(const float4*)&shB[k * 128 + tx * 8];
        float4 b1v = *(const float4*)&shB[k * 128 + tx * 8 + 4];
        float bfr[8] = {b0.x, b0.y, b0.z, b0.w, b1v.x, b1v.y, b1v.z, b1v.w};
#pragma unroll
        for (int j = 0; j < 8; ++j) {
            acc[0][j] = fmaf(a0, bfr[j], acc[0][j]);
            acc[1][j] = fmaf(a1, bfr[j], acc[1][j]);
        }
    }
    float a = *a_p;
#pragma unroll
    for (int i = 0; i < 2; ++i)
#pragma unroll
        for (int j = 0; j < 8; ++j) {
            float v = acc[i][j] + b1[tx * 8 + j];
            v = (v >= 0.f) ? v : a * v;
            shA[(ty * 2 + i) * 129 + tx * 8 + j] = v;
            acc[i][j] = 0.f;
        }

    for (int kc = 0; kc < HH_; kc += 32) {
        __syncthreads();
        for (int idx = tid; idx < 32 * 128; idx += 256) shB[idx] = W2[kc * 128 + idx];
        __syncthreads();
#pragma unroll 4
        for (int k = 0; k < 32; ++k) {
            float a0 = shA[(ty * 2 + 0) * 129 + kc + k];
            float a1 = shA[(ty * 2 + 1) * 129 + kc + k];
            float4 b0 = *(const float4*)&shB[k * 128 + tx * 8];
            float4 b1v = *(const float4*)&shB[k * 128 + tx * 8 + 4];
            float bfr[8] = {b0.x, b0.y, b0.z, b0.w, b1v.x, b1v.y, b1v.z, b1v.w};
#pragma unroll
            for (int j = 0; j < 8; ++j) {
                acc[0][j] = fmaf(a0, bfr[j], acc[0][j]);
                acc[1][j] = fmaf(a1, bfr[j], acc[1][j]);
            }
        }
    }
#pragma unroll
    for (int i = 0; i < 2; ++i) {
        int row = base + ty * 2 + i;
#pragma unroll
        for (int j = 0; j < 8; ++j)
            g_cx[row * HH_ + tx * 8 + j] = acc[i][j] + b2[tx * 8 + j];
    }
}

// ---------------------------------------------------------------------------
// K_edge: persistent, producer/consumer warp-specialized, double-buffered A.
// 512 threads: tid<256 = consumers (MMA+epilogue), tid>=256 = producers (h1).
// smem layout (bytes):
//   AH0=0        AH1=34816    (h1 hi, [128][136] f16, 2 bufs)
//   AL0=69632    AL1=104448   (h1 lo)
//   BH=139264    BL=174080    (W2^T hi/lo [n][k])
//   EA0=208896   EA1=210944   ([128][4] f32, 2 bufs)
//   SRC0=212992  SRC1=213504  DST0=214016  DST1=214528
//   B2C=215040   (128 f32)    total 215552
__global__ void __launch_bounds__(512, 1)
k_edge(const float* __restrict__ ea, const int* __restrict__ ei32,
       const float* __restrict__ W1, const float* __restrict__ b1,
       const float* __restrict__ a_p, const float* __restrict__ b2,
       int ntiles)
{
    extern __shared__ char smc[];
    float* shB2c = (float*)(smc + 215040);

    int tid = threadIdx.x;
    int lane = tid & 31;
    int is64 = g_is64;
    float a = *a_p;

    // one-time loads (all threads)
    {
        const uint4* wh4 = (const uint4*)g_W2h;
        const uint4* wl4 = (const uint4*)g_W2l;
        for (int idx = tid; idx < 2048; idx += 512) {
            int n = idx >> 4, ko = (idx & 15) * 8;
            *(uint4*)(smc + 139264 + (n * LDAH_ + ko) * 2) = wh4[idx];
            *(uint4*)(smc + 174080 + (n * LDAH_ + ko) * 2) = wl4[idx];
        }
        if (tid < 128) shB2c[tid] = b2[tid];
    }

    int iters = (ntiles - blockIdx.x + gridDim.x - 1) / gridDim.x;

    if (tid >= 256) {
        // ---------------- PRODUCER ----------------
        int ptid = tid - 256;
        int jp = (ptid & 63) * 2;      // column pair
        int eoff = ptid >> 6;          // 0..3
        float w1a[4], w1b[4];
#pragma unroll
        for (int k = 0; k < 4; ++k) {
            w1a[k] = W1[k * 128 + jp];
            w1b[k] = W1[k * 128 + jp + 1];
        }
        float b1a = b1[jp], b1b = b1[jp + 1];

        // fill buffer nb with tile t
        auto fill = [&](int nb, int t) {
            int e0 = t * 128;
            float* shEA = (float*)(smc + 208896 + nb * 2048);
            int* shSrc = (int*)(smc + 212992 + nb * 512);
            int* shDst = (int*)(smc + 214016 + nb * 512);
            for (int idx = ptid; idx < 512; idx += 256) shEA[idx] = ea[e0 * 4 + idx];
            if (ptid < 128) {
                if (is64) {
                    shSrc[ptid] = ei32[2 * (e0 + ptid)];
                    shDst[ptid] = ei32[2 * (EE_ + e0 + ptid)];
                } else {
                    shSrc[ptid] = ei32[e0 + ptid];
                    shDst[ptid] = ei32[EE_ + e0 + ptid];
                }
            }
            asm volatile("bar.sync 1, 256;" ::: "memory");
            char* pAh = smc + nb * 34816;
            char* pAl = smc + 69632 + nb * 34816;
#pragma unroll 4
            for (int k = 0; k < 32; ++k) {
                int e = eoff + 4 * k;
                float4 er = *(const float4*)&shEA[e * 4];
                float v0 = b1a, v1 = b1b;
                v0 = fmaf(er.x, w1a[0], v0); v1 = fmaf(er.x, w1b[0], v1);
                v0 = fmaf(er.y, w1a[1], v0); v1 = fmaf(er.y, w1b[1], v1);
                v0 = fmaf(er.z, w1a[2], v0); v1 = fmaf(er.z, w1b[2], v1);
                v0 = fmaf(er.w, w1a[3], v0); v1 = fmaf(er.w, w1b[3], v1);
                v0 = (v0 >= 0.f) ? v0 : a * v0;
                v1 = (v1 >= 0.f) ? v1 : a * v1;
                __half h0 = __float2half_rn(v0), h1 = __float2half_rn(v1);
                __half l0 = __float2half_rn(v0 - __half2float(h0));
                __half l1 = __float2half_rn(v1 - __half2float(h1));
                uint32_t hw = __half_as_ushort(h0) | ((uint32_t)__half_as_ushort(h1) << 16);
                uint32_t lw = __half_as_ushort(l0) | ((uint32_t)__half_as_ushort(l1) << 16);
                *(uint32_t*)(pAh + (e * LDAH_ + jp) * 2) = hw;
                *(uint32_t*)(pAl + (e * LDAH_ + jp) * 2) = lw;
            }
        };

        fill(0, blockIdx.x);           // prologue
        __syncthreads();
        for (int i = 0; i < iters; ++i) {
            int nt = i + 1;
            if (nt < iters) fill(nt & 1, blockIdx.x + nt * gridDim.x);
            __syncthreads();
        }
    } else {
        // ---------------- CONSUMER ----------------
        int w = tid >> 5;
        int wm = (w >> 2) * 64, wn = (w & 3) * 32;
        uint32_t sBh = smem_u32(smc + 139264);
        uint32_t sBl = smem_u32(smc + 174080);
        int cc = (lane & 3) * 2;

        __syncthreads();               // matches producer prologue; orders shB2c writes

        // loop-invariant b2 values (AFTER the barrier — shB2c now visible)
        float b2v[4][2];
#pragma unroll
        for (int nt = 0; nt < 4; ++nt) {
            int c = wn + nt * 8 + cc;
            b2v[nt][0] = shB2c[c];
            b2v[nt][1] = shB2c[c + 1];
        }

        for (int i = 0; i < iters; ++i) {
            int cb = i & 1;
            uint32_t sAh = smem_u32(smc + cb * 34816);
            uint32_t sAl = smem_u32(smc + 69632 + cb * 34816);
            int* shSrc = (int*)(smc + 212992 + cb * 512);
            int* shDst = (int*)(smc + 214016 + cb * 512);

            float acc[4][4][4] = {};
            mma_tile_3x(acc, sAh, sAl, sBh, sBl, wm, wn, lane);

            // epilogue directly from fragment layout
            int r0 = lane >> 2;
#pragma unroll
            for (int mt = 0; mt < 4; ++mt) {
                int rA = wm + mt * 16 + r0;
                int rB = rA + 8;
                int sA = shSrc[rA], dA = shDst[rA];
                int sB = shSrc[rB], dB = shDst[rB];
#pragma unroll
                for (int nt = 0; nt < 4; ++nt) {
                    int c = wn + nt * 8 + cc;
                    float2 cxA = *(const float2*)&g_cx[sA * HH_ + c];
                    float2 cxB = *(const float2*)&g_cx[sB * HH_ + c];
                    float m0 = fmaxf(0.f, acc[mt][nt][0] + b2v[nt][0] + cxA.x);
                    float m1 = fmaxf(0.f, acc[mt][nt][1] + b2v[nt][1] + cxA.y);
                    float m2 = fmaxf(0.f, acc[mt][nt][2] + b2v[nt][0] + cxB.x);
                    float m3 = fmaxf(0.f, acc[mt][nt][3] + b2v[nt][1] + cxB.y);
                    red_add_v2(&g_agg[dA * HH_ + c], m0, m1);
                    red_add_v2(&g_agg[dB * HH_ + c], m2, m3);
                }
            }
            __syncthreads();
        }
    }
}

// ---------------------------------------------------------------------------
// K_mlp: 256 CTAs x 32 rows
__global__ void __launch_bounds__(256)
k_mlp(const float* __restrict__ W1, const float* __restrict__ b1,
      const float* __restrict__ a_p,
      const float* __restrict__ W2, const float* __restrict__ b2,
      const float* __restrict__ eps_p, float* __restrict__ out_z)
{
    __shared__ float shA[32 * 129];
    __shared__ float shB[32 * 128];
    int tid = threadIdx.x;
    int tx = tid & 15, ty = tid >> 4;
    int base = blockIdx.x * 32;

    float ep = 1.0f + *eps_p;
    for (int idx = tid; idx < 32 * 128; idx += 256) {
        int r = idx >> 7, k = idx & 127;
        int g = (base + r) * HH_ + k;
        shA[r * 129 + k] = ep * g_cx[g] + g_agg[g];
    }

    float acc[2][8];
#pragma unroll
    for (int i = 0; i < 2; ++i)
#pragma unroll
        for (int j = 0; j < 8; ++j) acc[i][j] = 0.f;

    for (int kc = 0; kc < HH_; kc += 32) {
        __syncthreads();
        for (int idx = tid; idx < 32 * 128; idx += 256) shB[idx] = W1[kc * 128 + idx];
        __syncthreads();
#pragma unroll 4
        for (int k = 0; k < 32; ++k) {
            float a0 = shA[(ty * 2 + 0) * 129 + kc + k];
            float a1 = shA[(ty * 2 + 1) * 129 + kc + k];
            float4 b0 = *(const float4*)&shB[k * 128 + tx * 8];
            float4 b1v = *(const float4*)&shB[k * 128 + tx * 8 + 4];
            float bfr[8] = {b0.x, b0.y, b0.z, b0.w, b1v.x, b1v.y, b1v.z, b1v.w};
#pragma unroll
            for (int j = 0; j < 8; ++j) {
                acc[0][j] = fmaf(a0, bfr[j], acc[0][j]);
                acc[1][j] = fmaf(a1, bfr[j], acc[1][j]);
            }
        }
    }

    float a = *a_p;
    __syncthreads();
#pragma unroll
    for (int i = 0; i < 2; ++i)
#pragma unroll
        for (int j = 0; j < 8; ++j) {
            float v = acc[i][j] + b1[tx * 8 + j];
            v = (v >= 0.f) ? v : a * v;
            shA[(ty * 2 + i) * 129 + tx * 8 + j] = v;
            acc[i][j] = 0.f;
        }

    for (int kc = 0; kc < HH_; kc += 32) {
        __syncthreads();
        for (int idx = tid; idx < 32 * 128; idx += 256) shB[idx] = W2[kc * 128 + idx];
        __syncthreads();
#pragma unroll 4
        for (int k = 0; k < 32; ++k) {
            float a0 = shA[(ty * 2 + 0) * 129 + kc + k];
            float a1 = shA[(ty * 2 + 1) * 129 + kc + k];
            float4 b0 = *(const float4*)&shB[k * 128 + tx * 8];
            float4 b1v = *(const float4*)&shB[k * 128 + tx * 8 + 4];
            float bfr[8] = {b0.x, b0.y, b0.z, b0.w, b1v.x, b1v.y, b1v.z, b1v.w};
#pragma unroll
            for (int j = 0; j < 8; ++j) {
                acc[0][j] = fmaf(a0, bfr[j], acc[0][j]);
                acc[1][j] = fmaf(a1, bfr[j], acc[1][j]);
            }
        }
    }

#pragma unroll
    for (int i = 0; i < 2; ++i) {
        int row = base + ty * 2 + i;
#pragma unroll
        for (int j = 0; j < 8; ++j) {
            float v = acc[i][j] + b2[tx * 8 + j];
            int g = row * HH_ + tx * 8 + j;
            g_z[g] = v;
            out_z[g] = v;
            __half h = __float2half_rn(v);
            g_zh[g] = h;
            g_zl[g] = __float2half_rn(v - __half2float(h));
        }
    }
}

// ---------------------------------------------------------------------------
__global__ void k_p(const float* __restrict__ pW, const float* __restrict__ pb,
                    float* __restrict__ out_p)
{
    int tid = threadIdx.x;
    int grp = tid >> 4, lane = tid & 15;
    int node = blockIdx.x * 8 + grp;
    const float4* z4 = (const float4*)&g_z[node * HH_];
    float v = pb[lane];
#pragma unroll 8
    for (int k4 = 0; k4 < 32; ++k4) {
        float4 zz = z4[k4];
        int kb = k4 * 4;
        v += zz.x * pW[(kb + 0) * NCC_ + lane];
        v += zz.y * pW[(kb + 1) * NCC_ + lane];
        v += zz.z * pW[(kb + 2) * NCC_ + lane];
        v += zz.w * pW[(kb + 3) * NCC_ + lane];
    }
    float m = v;
#pragma unroll
    for (int off = 8; off > 0; off >>= 1)
        m = fmaxf(m, __shfl_xor_sync(0xffffffffu, m, off, 16));
    float e = expf(v - m);
    float s = e;
#pragma unroll
    for (int off = 8; off > 0; off >>= 1)
        s += __shfl_xor_sync(0xffffffffu, s, off, 16);
    out_p[node * NCC_ + lane] = e / s;
}

// ---------------------------------------------------------------------------
// K_ahat: A_hat = z z^T, HMMA fp16-split (pipelined), symmetric mirror
__global__ void __launch_bounds__(256, 1)
k_ahat(float* __restrict__ outA)
{
    int bi = blockIdx.y, bj = blockIdx.x;
    if (bj < bi) return;

    extern __shared__ char smc[];
    __half* shAh = (__half*)smc;
    __half* shAl = shAh + 128 * LDAH_;
    __half* shBh = (__half*)(smc + 69632);
    __half* shBl = shBh + 128 * LDAH_;
    int tid = threadIdx.x;

    const uint4* zh4 = (const uint4*)g_zh;
    const uint4* zl4 = (const uint4*)g_zl;
    for (int idx = tid; idx < 2048; idx += 256) {
        int r = idx >> 4, kv = idx & 15;
        int ko = kv * 8;
        *(uint4*)&shAh[r * LDAH_ + ko] = zh4[(bi * 128 + r) * 16 + kv];
        *(uint4*)&shAl[r * LDAH_ + ko] = zl4[(bi * 128 + r) * 16 + kv];
        *(uint4*)&shBh[r * LDAH_ + ko] = zh4[(bj * 128 + r) * 16 + kv];
        *(uint4*)&shBl[r * LDAH_ + ko] = zl4[(bj * 128 + r) * 16 + kv];
    }
    __syncthreads();

    float acc[4][4][4] = {};
    int lane = tid & 31, w = tid >> 5;
    int wm = (w >> 2) * 64, wn = (w & 3) * 32;
    mma_tile_3x(acc, smem_u32(shAh), smem_u32(shAl), smem_u32(shBh), smem_u32(shBl),
                wm, wn, lane);

    __syncthreads();
    float* shAcc = (float*)smc;
    stage_acc(shAcc, acc, wm, wn, lane);
    __syncthreads();

    int tx = tid & 15, ty = tid >> 4;
    const size_t Ns = NN_;
#pragma unroll
    for (int i = 0; i < 8; ++i) {
        int r = ty * 8 + i;
        const float* row = &shAcc[r * 132 + tx * 8];
        float4 w0 = make_float4(row[0], row[1], row[2], row[3]);
        float4 w1 = make_float4(row[4], row[5], row[6], row[7]);
        size_t go = (size_t)(bi * 128 + r) * Ns + bj * 128 + tx * 8;
        *(float4*)&outA[go] = w0;
        *(float4*)&outA[go + 4] = w1;
    }
    if (bi != bj) {
#pragma unroll
        for (int i = 0; i < 8; ++i) {
            int u = ty * 8 + i;
            float4 w0 = make_float4(shAcc[(tx * 8 + 0) * 132 + u],
                                    shAcc[(tx * 8 + 1) * 132 + u],
                                    shAcc[(tx * 8 + 2) * 132 + u],
                                    shAcc[(tx * 8 + 3) * 132 + u]);
            float4 w1 = make_float4(shAcc[(tx * 8 + 4) * 132 + u],
                                    shAcc[(tx * 8 + 5) * 132 + u],
                                    shAcc[(tx * 8 + 6) * 132 + u],
                                    shAcc[(tx * 8 + 7) * 132 + u]);
            size_t go = (size_t)(bj * 128 + u) * Ns + bi * 128 + tx * 8;
            *(float4*)&outA[go] = w0;
            *(float4*)&outA[go + 4] = w1;
        }
    }
}

// ---------------------------------------------------------------------------
extern "C" void kernel_launch(void* const* d_in, const int* in_sizes, int n_in,
                              void* d_out, int out_size)
{
    const float* x    = (const float*)d_in[0];
    const float* ea   = (const float*)d_in[1];
    const int*   ei32 = (const int*)  d_in[2];
    const float* neW1 = (const float*)d_in[3];
    const float* neb1 = (const float*)d_in[4];
    const float* nea  = (const float*)d_in[5];
    const float* neW2 = (const float*)d_in[6];
    const float* neb2 = (const float*)d_in[7];
    const float* eeW1 = (const float*)d_in[8];
    const float* eeb1 = (const float*)d_in[9];
    const float* eea  = (const float*)d_in[10];
    const float* eeW2 = (const float*)d_in[11];
    const float* eeb2 = (const float*)d_in[12];
    const float* gW1  = (const float*)d_in[13];
    const float* gb1  = (const float*)d_in[14];
    const float* ga   = (const float*)d_in[15];
    const float* gW2  = (const float*)d_in[16];
    const float* gb2  = (const float*)d_in[17];
    const float* eps  = (const float*)d_in[18];
    const float* pW   = (const float*)d_in[19];
    const float* pb   = (const float*)d_in[20];

    float* out   = (float*)d_out;
    float* out_A = out;
    float* out_p = out + (size_t)NN_ * NN_;
    float* out_z = out_p + (size_t)NN_ * NCC_;

    const int smem_edge = 215552;
    const int smem_ahat = 139264;

    cudaFuncSetAttribute(k_edge, cudaFuncAttributeMaxDynamicSharedMemorySize, smem_edge);
    cudaFuncSetAttribute(k_ahat, cudaFuncAttributeMaxDynamicSharedMemorySize, smem_ahat);

    k_prep<<<512, 256>>>(ei32);
    k_node_enc<<<NN_ / 32, 256>>>(x, neW1, neb1, nea, neW2, neb2);
    k_split_w2<<<64, 256>>>(eeW2);
    k_edge<<<148, 512, smem_edge>>>(ea, ei32, eeW1, eeb1, eea, eeb2, EE_ / 128);
    k_mlp<<<NN_ / 32, 256>>>(gW1, gb1, ga, gW2, gb2, eps, out_z);
    k_p<<<NN_ / 8, 128>>>(pW, pb, out_p);
    k_ahat<<<dim3(NN_ / 128, NN_ / 128), 256, smem_ahat>>>(out_A);
}

// round 15
// speedup vs baseline: 1.0070x; 1.0070x over previous
#include <cuda_runtime.h>
#include <cuda_fp16.h>
#include <cstdint>

#define NN_ 8192
#define EE_ 524288
#define HH_ 128
#define IND_ 32
#define NCC_ 16

// Device scratch (static, no allocations)
__device__ __align__(16) float g_cx[NN_ * HH_];
__device__ __align__(16) float g_agg[NN_ * HH_];
__device__ __align__(16) float g_z[NN_ * HH_];
__device__ __align__(16) __half g_zh[NN_ * HH_];
__device__ __align__(16) __half g_zl[NN_ * HH_];
__device__ __align__(16) __half g_W2h[HH_ * HH_];  // eeW2^T [n][k] hi
__device__ __align__(16) __half g_W2l[HH_ * HH_];  // eeW2^T [n][k] lo
__device__ int g_is64;

// ---------------------------------------------------------------------------
__device__ __forceinline__ void red_add_v2(float* addr, float x, float y) {
    asm volatile("red.global.add.v2.f32 [%0], {%1,%2};"
                 :: "l"(addr), "f"(x), "f"(y) : "memory");
}
__device__ __forceinline__ uint32_t smem_u32(const void* p) {
    return (uint32_t)__cvta_generic_to_shared(p);
}
__device__ __forceinline__ void ldmx4(uint32_t r[4], uint32_t addr) {
    asm volatile("ldmatrix.sync.aligned.m8n8.x4.shared.b16 {%0,%1,%2,%3}, [%4];"
                 : "=r"(r[0]), "=r"(r[1]), "=r"(r[2]), "=r"(r[3]) : "r"(addr));
}
__device__ __forceinline__ void mma16816(float c[4], const uint32_t a[4],
                                         uint32_t b0, uint32_t b1) {
    asm volatile("mma.sync.aligned.m16n8k16.row.col.f32.f16.f16.f32 "
                 "{%0,%1,%2,%3}, {%4,%5,%6,%7}, {%8,%9}, {%0,%1,%2,%3};"
                 : "+f"(c[0]), "+f"(c[1]), "+f"(c[2]), "+f"(c[3])
                 : "r"(a[0]), "r"(a[1]), "r"(a[2]), "r"(a[3]), "r"(b0), "r"(b1));
}

#define LDAH_ 136
// 3-term split MMA, 8 warps as 2(m)x4(n), warp tile 64x32, reg-pipelined A.
__device__ __forceinline__ void mma_tile_3x(
    float acc[4][4][4], uint32_t sAh, uint32_t sAl, uint32_t sBh, uint32_t sBl,
    int wm, int wn, int lane)
{
    int lrow = lane & 15;
    int lcol = (lane >> 4) * 8;
    uint32_t ah[2][4], al[2][4];
    {   // prologue: A(ks=0, mt=0)
        uint32_t off = (uint32_t)(((wm + lrow) * LDAH_ + lcol) * 2);
        ldmx4(ah[0], sAh + off);
        ldmx4(al[0], sAl + off);
    }
#pragma unroll 1
    for (int ks = 0; ks < 8; ++ks) {
        int kk = ks * 16;
        uint32_t bh[2][4], bl[2][4];
#pragma unroll
        for (int bt = 0; bt < 2; ++bt) {
            uint32_t off = (uint32_t)(((wn + bt * 16 + lrow) * LDAH_ + kk + lcol) * 2);
            ldmx4(bh[bt], sBh + off);
            ldmx4(bl[bt], sBl + off);
        }
#pragma unroll
        for (int mt = 0; mt < 4; ++mt) {
            int cur = mt & 1, nxt = cur ^ 1;
            if (mt < 3) {
                uint32_t off = (uint32_t)(((wm + (mt + 1) * 16 + lrow) * LDAH_ + kk + lcol) * 2);
                ldmx4(ah[nxt], sAh + off);
                ldmx4(al[nxt], sAl + off);
            } else if (ks < 7) {
                uint32_t off = (uint32_t)(((wm + lrow) * LDAH_ + kk + 16 + lcol) * 2);
                ldmx4(ah[nxt], sAh + off);
                ldmx4(al[nxt], sAl + off);
            }
#pragma unroll
            for (int nt = 0; nt < 4; ++nt) {
                int bt = nt >> 1, sel = nt & 1;
                mma16816(acc[mt][nt], ah[cur], bh[bt][sel], bh[bt][sel + 2]);
            }
#pragma unroll
            for (int nt = 0; nt < 4; ++nt) {
                int bt = nt >> 1, sel = nt & 1;
                mma16816(acc[mt][nt], ah[cur], bl[bt][sel], bl[bt][sel + 2]);
            }
#pragma unroll
            for (int nt = 0; nt < 4; ++nt) {
                int bt = nt >> 1, sel = nt & 1;
                mma16816(acc[mt][nt], al[cur], bh[bt][sel], bh[bt][sel + 2]);
            }
        }
    }
}

__device__ __forceinline__ void stage_acc(float* shAcc, float acc[4][4][4],
                                          int wm, int wn, int lane)
{
#pragma unroll
    for (int mt = 0; mt < 4; ++mt)
#pragma unroll
        for (int nt = 0; nt < 4; ++nt) {
            int r = wm + mt * 16 + (lane >> 2);
            int c = wn + nt * 8 + (lane & 3) * 2;
            shAcc[r * 132 + c] = acc[mt][nt][0];
            shAcc[r * 132 + c + 1] = acc[mt][nt][1];
            shAcc[(r + 8) * 132 + c] = acc[mt][nt][2];
            shAcc[(r + 8) * 132 + c + 1] = acc[mt][nt][3];
        }
}

// ---------------------------------------------------------------------------
__global__ void k_prep(const int* __restrict__ ei32) {
    if (blockIdx.x == 0 && threadIdx.x == 0) {
        int all0 = 1;
        for (int i = 0; i < 64; ++i)
            if (ei32[2 * i + 1] != 0) { all0 = 0; break; }
        g_is64 = all0;
    }
    int idx = blockIdx.x * blockDim.x + threadIdx.x;
    float4* p = reinterpret_cast<float4*>(g_agg);
    int n4 = NN_ * HH_ / 4;
    for (int i = idx; i < n4; i += gridDim.x * blockDim.x)
        p[i] = make_float4(0.f, 0.f, 0.f, 0.f);
}

__global__ void k_split_w2(const float* __restrict__ W2) {
    int idx = blockIdx.x * 256 + threadIdx.x;
    int k = idx >> 7, n = idx & 127;
    float v = W2[k * 128 + n];
    __half h = __float2half_rn(v);
    g_W2h[n * 128 + k] = h;
    g_W2l[n * 128 + k] = __float2half_rn(v - __half2float(h));
}

// ---------------------------------------------------------------------------
// K_node: 256 CTAs x 32 rows
__global__ void __launch_bounds__(256)
k_node_enc(const float* __restrict__ x,
           const float* __restrict__ W1, const float* __restrict__ b1,
           const float* __restrict__ a_p,
           const float* __restrict__ W2, const float* __restrict__ b2)
{
    __shared__ float shA[32 * 129];
    __shared__ float shB[32 * 128];
    __shared__ float shX[32 * 33];
    int tid = threadIdx.x;
    int tx = tid & 15, ty = tid >> 4;
    int base = blockIdx.x * 32;

    for (int idx = tid; idx < 32 * 32; idx += 256) {
        int r = idx >> 5, k = idx & 31;
        shX[r * 33 + k] = x[(base + r) * IND_ + k];
    }
    for (int idx = tid; idx < 32 * 128; idx += 256) shB[idx] = W1[idx];
    __syncthreads();

    float acc[2][8];
#pragma unroll
    for (int i = 0; i < 2; ++i)
#pragma unroll
        for (int j = 0; j < 8; ++j) acc[i][j] = 0.f;

#pragma unroll 4
    for (int k = 0; k < 32; ++k) {
        float a0 = shX[(ty * 2 + 0) * 33 + k];
        float a1 = shX[(ty * 2 + 1) * 33 + k];
        float4 b0 = *(const float4*)&shB[k * 128 + tx * 8];
        float4 b1v = *(const float4*)&shB[k * 128 + tx * 8 + 4];
        float bfr[8] = {b0.x, b0.y, b0.z, b0.w, b1v.x, b1v.y, b1v.z, b1v.w};
#pragma unroll
        for (int j = 0; j < 8; ++j) {
            acc[0][j] = fmaf(a0, bfr[j], acc[0][j]);
            acc[1][j] = fmaf(a1, bfr[j], acc[1][j]);
        }
    }
    float a = *a_p;
#pragma unroll
    for (int i = 0; i < 2; ++i)
#pragma unroll
        for (int j = 0; j < 8; ++j) {
            float v = acc[i][j] + b1[tx * 8 + j];
            v = (v >= 0.f) ? v : a * v;
            shA[(ty * 2 + i) * 129 + tx * 8 + j] = v;
            acc[i][j] = 0.f;
        }

    for (int kc = 0; kc < HH_; kc += 32) {
        __syncthreads();
        for (int idx = tid; idx < 32 * 128; idx += 256) shB[idx] = W2[kc * 128 + idx];
        __syncthreads();
#pragma unroll 4
        for (int k = 0; k < 32; ++k) {
            float a0 = shA[(ty * 2 + 0) * 129 + kc + k];
            float a1 = shA[(ty * 2 + 1) * 129 + kc + k];
            float4 b0 = *(const float4*)&shB[k * 128 + tx * 8];
            float4 b1v = *(const float4*)&shB[k * 128 + tx * 8 + 4];
            float bfr[8] = {b0.x, b0.y, b0.z, b0.w, b1v.x, b1v.y, b1v.z, b1v.w};
#pragma unroll
            for (int j = 0; j < 8; ++j) {
                acc[0][j] = fmaf(a0, bfr[j], acc[0][j]);
                acc[1][j] = fmaf(a1, bfr[j], acc[1][j]);
            }
        }
    }
#pragma unroll
    for (int i = 0; i < 2; ++i) {
        int row = base + ty * 2 + i;
#pragma unroll
        for (int j = 0; j < 8; ++j)
            g_cx[row * HH_ + tx * 8 + j] = acc[i][j] + b2[tx * 8 + j];
    }
}

// ---------------------------------------------------------------------------
// K_edge: persistent, producer/consumer warp-specialized, double-buffered A.
// (unchanged from R14 passing version)
__global__ void __launch_bounds__(512, 1)
k_edge(const float* __restrict__ ea, const int* __restrict__ ei32,
       const float* __restrict__ W1, const float* __restrict__ b1,
       const float* __restrict__ a_p, const float* __restrict__ b2,
       int ntiles)
{
    extern __shared__ char smc[];
    float* shB2c = (float*)(smc + 215040);

    int tid = threadIdx.x;
    int lane = tid & 31;
    int is64 = g_is64;
    float a = *a_p;

    {
        const uint4* wh4 = (const uint4*)g_W2h;
        const uint4* wl4 = (const uint4*)g_W2l;
        for (int idx = tid; idx < 2048; idx += 512) {
            int n = idx >> 4, ko = (idx & 15) * 8;
            *(uint4*)(smc + 139264 + (n * LDAH_ + ko) * 2) = wh4[idx];
            *(uint4*)(smc + 174080 + (n * LDAH_ + ko) * 2) = wl4[idx];
        }
        if (tid < 128) shB2c[tid] = b2[tid];
    }

    int iters = (ntiles - blockIdx.x + gridDim.x - 1) / gridDim.x;

    if (tid >= 256) {
        // ---------------- PRODUCER ----------------
        int ptid = tid - 256;
        int jp = (ptid & 63) * 2;
        int eoff = ptid >> 6;
        float w1a[4], w1b[4];
#pragma unroll
        for (int k = 0; k < 4; ++k) {
            w1a[k] = W1[k * 128 + jp];
            w1b[k] = W1[k * 128 + jp + 1];
        }
        float b1a = b1[jp], b1b = b1[jp + 1];

        auto fill = [&](int nb, int t) {
            int e0 = t * 128;
            float* shEA = (float*)(smc + 208896 + nb * 2048);
            int* shSrc = (int*)(smc + 212992 + nb * 512);
            int* shDst = (int*)(smc + 214016 + nb * 512);
            for (int idx = ptid; idx < 512; idx += 256) shEA[idx] = ea[e0 * 4 + idx];
            if (ptid < 128) {
                if (is64) {
                    shSrc[ptid] = ei32[2 * (e0 + ptid)];
                    shDst[ptid] = ei32[2 * (EE_ + e0 + ptid)];
                } else {
                    shSrc[ptid] = ei32[e0 + ptid];
                    shDst[ptid] = ei32[EE_ + e0 + ptid];
                }
            }
            asm volatile("bar.sync 1, 256;" ::: "memory");
            char* pAh = smc + nb * 34816;
            char* pAl = smc + 69632 + nb * 34816;
#pragma unroll 4
            for (int k = 0; k < 32; ++k) {
                int e = eoff + 4 * k;
                float4 er = *(const float4*)&shEA[e * 4];
                float v0 = b1a, v1 = b1b;
                v0 = fmaf(er.x, w1a[0], v0); v1 = fmaf(er.x, w1b[0], v1);
                v0 = fmaf(er.y, w1a[1], v0); v1 = fmaf(er.y, w1b[1], v1);
                v0 = fmaf(er.z, w1a[2], v0); v1 = fmaf(er.z, w1b[2], v1);
                v0 = fmaf(er.w, w1a[3], v0); v1 = fmaf(er.w, w1b[3], v1);
                v0 = (v0 >= 0.f) ? v0 : a * v0;
                v1 = (v1 >= 0.f) ? v1 : a * v1;
                __half h0 = __float2half_rn(v0), h1 = __float2half_rn(v1);
                __half l0 = __float2half_rn(v0 - __half2float(h0));
                __half l1 = __float2half_rn(v1 - __half2float(h1));
                uint32_t hw = __half_as_ushort(h0) | ((uint32_t)__half_as_ushort(h1) << 16);
                uint32_t lw = __half_as_ushort(l0) | ((uint32_t)__half_as_ushort(l1) << 16);
                *(uint32_t*)(pAh + (e * LDAH_ + jp) * 2) = hw;
                *(uint32_t*)(pAl + (e * LDAH_ + jp) * 2) = lw;
            }
        };

        fill(0, blockIdx.x);
        __syncthreads();
        for (int i = 0; i < iters; ++i) {
            int nt = i + 1;
            if (nt < iters) fill(nt & 1, blockIdx.x + nt * gridDim.x);
            __syncthreads();
        }
    } else {
        // ---------------- CONSUMER ----------------
        int w = tid >> 5;
        int wm = (w >> 2) * 64, wn = (w & 3) * 32;
        uint32_t sBh = smem_u32(smc + 139264);
        uint32_t sBl = smem_u32(smc + 174080);
        int cc = (lane & 3) * 2;

        __syncthreads();

        float b2v[4][2];
#pragma unroll
        for (int nt = 0; nt < 4; ++nt) {
            int c = wn + nt * 8 + cc;
            b2v[nt][0] = shB2c[c];
            b2v[nt][1] = shB2c[c + 1];
        }

        for (int i = 0; i < iters; ++i) {
            int cb = i & 1;
            uint32_t sAh = smem_u32(smc + cb * 34816);
            uint32_t sAl = smem_u32(smc + 69632 + cb * 34816);
            int* shSrc = (int*)(smc + 212992 + cb * 512);
            int* shDst = (int*)(smc + 214016 + cb * 512);

            float acc[4][4][4] = {};
            mma_tile_3x(acc, sAh, sAl, sBh, sBl, wm, wn, lane);

            int r0 = lane >> 2;
#pragma unroll
            for (int mt = 0; mt < 4; ++mt) {
                int rA = wm + mt * 16 + r0;
                int rB = rA + 8;
                int sA = shSrc[rA], dA = shDst[rA];
                int sB = shSrc[rB], dB = shDst[rB];
#pragma unroll
                for (int nt = 0; nt < 4; ++nt) {
                    int c = wn + nt * 8 + cc;
                    float2 cxA = *(const float2*)&g_cx[sA * HH_ + c];
                    float2 cxB = *(const float2*)&g_cx[sB * HH_ + c];
                    float m0 = fmaxf(0.f, acc[mt][nt][0] + b2v[nt][0] + cxA.x);
                    float m1 = fmaxf(0.f, acc[mt][nt][1] + b2v[nt][1] + cxA.y);
                    float m2 = fmaxf(0.f, acc[mt][nt][2] + b2v[nt][0] + cxB.x);
                    float m3 = fmaxf(0.f, acc[mt][nt][3] + b2v[nt][1] + cxB.y);
                    red_add_v2(&g_agg[dA * HH_ + c], m0, m1);
                    red_add_v2(&g_agg[dB * HH_ + c], m2, m3);
                }
            }
            __syncthreads();
        }
    }
}

// ---------------------------------------------------------------------------
// K_mlp: 256 CTAs x 32 rows
__global__ void __launch_bounds__(256)
k_mlp(const float* __restrict__ W1, const float* __restrict__ b1,
      const float* __restrict__ a_p,
      const float* __restrict__ W2, const float* __restrict__ b2,
      const float* __restrict__ eps_p, float* __restrict__ out_z)
{
    __shared__ float shA[32 * 129];
    __shared__ float shB[32 * 128];
    int tid = threadIdx.x;
    int tx = tid & 15, ty = tid >> 4;
    int base = blockIdx.x * 32;

    float ep = 1.0f + *eps_p;
    for (int idx = tid; idx < 32 * 128; idx += 256) {
        int r = idx >> 7, k = idx & 127;
        int g = (base + r) * HH_ + k;
        shA[r * 129 + k] = ep * g_cx[g] + g_agg[g];
    }

    float acc[2][8];
#pragma unroll
    for (int i = 0; i < 2; ++i)
#pragma unroll
        for (int j = 0; j < 8; ++j) acc[i][j] = 0.f;

    for (int kc = 0; kc < HH_; kc += 32) {
        __syncthreads();
        for (int idx = tid; idx < 32 * 128; idx += 256) shB[idx] = W1[kc * 128 + idx];
        __syncthreads();
#pragma unroll 4
        for (int k = 0; k < 32; ++k) {
            float a0 = shA[(ty * 2 + 0) * 129 + kc + k];
            float a1 = shA[(ty * 2 + 1) * 129 + kc + k];
            float4 b0 = *(const float4*)&shB[k * 128 + tx * 8];
            float4 b1v = *(const float4*)&shB[k * 128 + tx * 8 + 4];
            float bfr[8] = {b0.x, b0.y, b0.z, b0.w, b1v.x, b1v.y, b1v.z, b1v.w};
#pragma unroll
            for (int j = 0; j < 8; ++j) {
                acc[0][j] = fmaf(a0, bfr[j], acc[0][j]);
                acc[1][j] = fmaf(a1, bfr[j], acc[1][j]);
            }
        }
    }

    float a = *a_p;
    __syncthreads();
#pragma unroll
    for (int i = 0; i < 2; ++i)
#pragma unroll
        for (int j = 0; j < 8; ++j) {
            float v = acc[i][j] + b1[tx * 8 + j];
            v = (v >= 0.f) ? v : a * v;
            shA[(ty * 2 + i) * 129 + tx * 8 + j] = v;
            acc[i][j] = 0.f;
        }

    for (int kc = 0; kc < HH_; kc += 32) {
        __syncthreads();
        for (int idx = tid; idx < 32 * 128; idx += 256) shB[idx] = W2[kc * 128 + idx];
        __syncthreads();
#pragma unroll 4
        for (int k = 0; k < 32; ++k) {
            float a0 = shA[(ty * 2 + 0) * 129 + kc + k];
            float a1 = shA[(ty * 2 + 1) * 129 + kc + k];
            float4 b0 = *(const float4*)&shB[k * 128 + tx * 8];
            float4 b1v = *(const float4*)&shB[k * 128 + tx * 8 + 4];
            float bfr[8] = {b0.x, b0.y, b0.z, b0.w, b1v.x, b1v.y, b1v.z, b1v.w};
#pragma unroll
            for (int j = 0; j < 8; ++j) {
                acc[0][j] = fmaf(a0, bfr[j], acc[0][j]);
                acc[1][j] = fmaf(a1, bfr[j], acc[1][j]);
            }
        }
    }

#pragma unroll
    for (int i = 0; i < 2; ++i) {
        int row = base + ty * 2 + i;
#pragma unroll
        for (int j = 0; j < 8; ++j) {
            float v = acc[i][j] + b2[tx * 8 + j];
            int g = row * HH_ + tx * 8 + j;
            g_z[g] = v;
            out_z[g] = v;
            __half h = __float2half_rn(v);
            g_zh[g] = h;
            g_zl[g] = __float2half_rn(v - __half2float(h));
        }
    }
}

// ---------------------------------------------------------------------------
__global__ void k_p(const float* __restrict__ pW, const float* __restrict__ pb,
                    float* __restrict__ out_p)
{
    int tid = threadIdx.x;
    int grp = tid >> 4, lane = tid & 15;
    int node = blockIdx.x * 8 + grp;
    const float4* z4 = (const float4*)&g_z[node * HH_];
    float v = pb[lane];
#pragma unroll 8
    for (int k4 = 0; k4 < 32; ++k4) {
        float4 zz = z4[k4];
        int kb = k4 * 4;
        v += zz.x * pW[(kb + 0) * NCC_ + lane];
        v += zz.y * pW[(kb + 1) * NCC_ + lane];
        v += zz.z * pW[(kb + 2) * NCC_ + lane];
        v += zz.w * pW[(kb + 3) * NCC_ + lane];
    }
    float m = v;
#pragma unroll
    for (int off = 8; off > 0; off >>= 1)
        m = fmaxf(m, __shfl_xor_sync(0xffffffffu, m, off, 16));
    float e = expf(v - m);
    float s = e;
#pragma unroll
    for (int off = 8; off > 0; off >>= 1)
        s += __shfl_xor_sync(0xffffffffu, s, off, 16);
    out_p[node * NCC_ + lane] = e / s;
}

// ---------------------------------------------------------------------------
// K_ahat: A_hat = z z^T. 512 threads, 128x256 output slab per CTA:
// two 128x128 column tiles (j0=2*bj2, j1=j0+1) sharing one A tile (rows bi).
// Warp groups: g = w>>3 handles tile g with the proven 8-warp 64x32 layout.
// smem: AH=0 AL=34816 | B0H=69632 B0L=104448 | B1H=139264 B1L=174080 (208896).
// Staging overlays: group g stages into smc + g*69632 after MMA completes.
__global__ void __launch_bounds__(512, 1)
k_ahat(float* __restrict__ outA)
{
    int bj2 = blockIdx.x, bi = blockIdx.y;
    int j0 = 2 * bj2, j1 = j0 + 1;
    if (j1 < bi) return;               // slab entirely below diagonal

    extern __shared__ char smc[];
    int tid = threadIdx.x;
    int lane = tid & 31, w = tid >> 5;
    int g = w >> 3, w8 = w & 7;
    int wm = (w8 >> 2) * 64, wn = (w8 & 3) * 32;

    const uint4* zh4 = (const uint4*)g_zh;
    const uint4* zl4 = (const uint4*)g_zl;
    for (int idx = tid; idx < 2048; idx += 512) {
        int r = idx >> 4, kv = idx & 15;
        uint32_t off = (uint32_t)((r * LDAH_ + kv * 8) * 2);
        *(uint4*)(smc + off)          = zh4[(bi * 128 + r) * 16 + kv];
        *(uint4*)(smc + 34816 + off)  = zl4[(bi * 128 + r) * 16 + kv];
        *(uint4*)(smc + 69632 + off)  = zh4[(j0 * 128 + r) * 16 + kv];
        *(uint4*)(smc + 104448 + off) = zl4[(j0 * 128 + r) * 16 + kv];
        *(uint4*)(smc + 139264 + off) = zh4[(j1 * 128 + r) * 16 + kv];
        *(uint4*)(smc + 174080 + off) = zl4[(j1 * 128 + r) * 16 + kv];
    }
    __syncthreads();

    int j = j0 + g;
    bool live = (j >= bi);             // uniform per warp-group
    float acc[4][4][4] = {};
    if (live)
        mma_tile_3x(acc, smem_u32(smc), smem_u32(smc + 34816),
                    smem_u32(smc + 69632 + g * 69632),
                    smem_u32(smc + 104448 + g * 69632), wm, wn, lane);
    __syncthreads();                   // all MMA reads done before overlay

    float* shAcc = (float*)(smc + g * 69632);  // g=0 over A, g=1 over B0
    if (live) stage_acc(shAcc, acc, wm, wn, lane);
    __syncthreads();

    int tx = tid & 15, ty = tid >> 4;  // ty 0..31
    const size_t Ns = NN_;
#pragma unroll
    for (int t = 0; t < 2; ++t) {
        int jt = j0 + t;
        if (jt < bi) continue;         // uniform across block
        const float* sa = (const float*)(smc + t * 69632);
#pragma unroll
        for (int i = 0; i < 4; ++i) {
            int r = ty + i * 32;
            const float* row = &sa[r * 132 + tx * 8];
            float4 w0 = make_float4(row[0], row[1], row[2], row[3]);
            float4 w1 = make_float4(row[4], row[5], row[6], row[7]);
            size_t go = (size_t)(bi * 128 + r) * Ns + (size_t)jt * 128 + tx * 8;
            *(float4*)&outA[go] = w0;
            *(float4*)&outA[go + 4] = w1;
        }
        if (jt > bi) {
#pragma unroll
            for (int i = 0; i < 4; ++i) {
                int u = ty + i * 32;
                float4 w0 = make_float4(sa[(tx * 8 + 0) * 132 + u],
                                        sa[(tx * 8 + 1) * 132 + u],
                                        sa[(tx * 8 + 2) * 132 + u],
                                        sa[(tx * 8 + 3) * 132 + u]);
                float4 w1 = make_float4(sa[(tx * 8 + 4) * 132 + u],
                                        sa[(tx * 8 + 5) * 132 + u],
                                        sa[(tx * 8 + 6) * 132 + u],
                                        sa[(tx * 8 + 7) * 132 + u]);
                size_t go = (size_t)(jt * 128 + u) * Ns + (size_t)bi * 128 + tx * 8;
                *(float4*)&outA[go] = w0;
                *(float4*)&outA[go + 4] = w1;
            }
        }
    }
}

// ---------------------------------------------------------------------------
extern "C" void kernel_launch(void* const* d_in, const int* in_sizes, int n_in,
                              void* d_out, int out_size)
{
    const float* x    = (const float*)d_in[0];
    const float* ea   = (const float*)d_in[1];
    const int*   ei32 = (const int*)  d_in[2];
    const float* neW1 = (const float*)d_in[3];
    const float* neb1 = (const float*)d_in[4];
    const float* nea  = (const float*)d_in[5];
    const float* neW2 = (const float*)d_in[6];
    const float* neb2 = (const float*)d_in[7];
    const float* eeW1 = (const float*)d_in[8];
    const float* eeb1 = (const float*)d_in[9];
    const float* eea  = (const float*)d_in[10];
    const float* eeW2 = (const float*)d_in[11];
    const float* eeb2 = (const float*)d_in[12];
    const float* gW1  = (const float*)d_in[13];
    const float* gb1  = (const float*)d_in[14];
    const float* ga   = (const float*)d_in[15];
    const float* gW2  = (const float*)d_in[16];
    const float* gb2  = (const float*)d_in[17];
    const float* eps  = (const float*)d_in[18];
    const float* pW   = (const float*)d_in[19];
    const float* pb   = (const float*)d_in[20];

    float* out   = (float*)d_out;
    float* out_A = out;
    float* out_p = out + (size_t)NN_ * NN_;
    float* out_z = out_p + (size_t)NN_ * NCC_;

    const int smem_edge = 215552;
    const int smem_ahat = 208896;

    cudaFuncSetAttribute(k_edge, cudaFuncAttributeMaxDynamicSharedMemorySize, smem_edge);
    cudaFuncSetAttribute(k_ahat, cudaFuncAttributeMaxDynamicSharedMemorySize, smem_ahat);

    k_prep<<<512, 256>>>(ei32);
    k_node_enc<<<NN_ / 32, 256>>>(x, neW1, neb1, nea, neW2, neb2);
    k_split_w2<<<64, 256>>>(eeW2);
    k_edge<<<148, 512, smem_edge>>>(ea, ei32, eeW1, eeb1, eea, eeb2, EE_ / 128);
    k_mlp<<<NN_ / 32, 256>>>(gW1, gb1, ga, gW2, gb2, eps, out_z);
    k_p<<<NN_ / 8, 128>>>(pW, pb, out_p);
    k_ahat<<<dim3(NN_ / 256, NN_ / 128), 512, smem_ahat>>>(out_A);
}

// round 16
// speedup vs baseline: 1.1576x; 1.1496x over previous
#include <cuda_runtime.h>
#include <cuda_fp16.h>
#include <cstdint>

#define NN_ 8192
#define EE_ 524288
#define HH_ 128
#define IND_ 32
#define NCC_ 16

// Device scratch (static, no allocations)
__device__ __align__(16) float g_cx[NN_ * HH_];
__device__ __align__(16) float g_agg[NN_ * HH_];
__device__ __align__(16) float g_z[NN_ * HH_];
__device__ __align__(16) __half g_zh[NN_ * HH_];
__device__ __align__(16) __half g_zl[NN_ * HH_];
__device__ __align__(16) __half g_W2h[HH_ * HH_];  // eeW2^T [n][k] hi
__device__ __align__(16) __half g_W2l[HH_ * HH_];  // eeW2^T [n][k] lo
__device__ int g_is64;

// ---------------------------------------------------------------------------
__device__ __forceinline__ void red_add_v2(float* addr, float x, float y) {
    asm volatile("red.global.add.v2.f32 [%0], {%1,%2};"
                 :: "l"(addr), "f"(x), "f"(y) : "memory");
}
__device__ __forceinline__ uint32_t smem_u32(const void* p) {
    return (uint32_t)__cvta_generic_to_shared(p);
}
__device__ __forceinline__ void ldmx4(uint32_t r[4], uint32_t addr) {
    asm volatile("ldmatrix.sync.aligned.m8n8.x4.shared.b16 {%0,%1,%2,%3}, [%4];"
                 : "=r"(r[0]), "=r"(r[1]), "=r"(r[2]), "=r"(r[3]) : "r"(addr));
}
__device__ __forceinline__ void mma16816(float c[4], const uint32_t a[4],
                                         uint32_t b0, uint32_t b1) {
    asm volatile("mma.sync.aligned.m16n8k16.row.col.f32.f16.f16.f32 "
                 "{%0,%1,%2,%3}, {%4,%5,%6,%7}, {%8,%9}, {%0,%1,%2,%3};"
                 : "+f"(c[0]), "+f"(c[1]), "+f"(c[2]), "+f"(c[3])
                 : "r"(a[0]), "r"(a[1]), "r"(a[2]), "r"(a[3]), "r"(b0), "r"(b1));
}

#define LDAH_ 136
// 2-term split, A single array (A-hi), B hi+lo: computes Ah*(Bh+Bl) = Ah*B.
// 8 warps as 2(m)x4(n), warp tile 64x32, reg-pipelined A.
__device__ __forceinline__ void mma_tile_2e(
    float acc[4][4][4], uint32_t sA, uint32_t sBh, uint32_t sBl,
    int wm, int wn, int lane)
{
    int lrow = lane & 15;
    int lcol = (lane >> 4) * 8;
    uint32_t ah[2][4];
    {
        uint32_t off = (uint32_t)(((wm + lrow) * LDAH_ + lcol) * 2);
        ldmx4(ah[0], sA + off);
    }
#pragma unroll 1
    for (int ks = 0; ks < 8; ++ks) {
        int kk = ks * 16;
        uint32_t bh[2][4], bl[2][4];
#pragma unroll
        for (int bt = 0; bt < 2; ++bt) {
            uint32_t off = (uint32_t)(((wn + bt * 16 + lrow) * LDAH_ + kk + lcol) * 2);
            ldmx4(bh[bt], sBh + off);
            ldmx4(bl[bt], sBl + off);
        }
#pragma unroll
        for (int mt = 0; mt < 4; ++mt) {
            int cur = mt & 1, nxt = cur ^ 1;
            if (mt < 3) {
                uint32_t off = (uint32_t)(((wm + (mt + 1) * 16 + lrow) * LDAH_ + kk + lcol) * 2);
                ldmx4(ah[nxt], sA + off);
            } else if (ks < 7) {
                uint32_t off = (uint32_t)(((wm + lrow) * LDAH_ + kk + 16 + lcol) * 2);
                ldmx4(ah[nxt], sA + off);
            }
#pragma unroll
            for (int nt = 0; nt < 4; ++nt) {
                int bt = nt >> 1, sel = nt & 1;
                mma16816(acc[mt][nt], ah[cur], bh[bt][sel], bh[bt][sel + 2]);
            }
#pragma unroll
            for (int nt = 0; nt < 4; ++nt) {
                int bt = nt >> 1, sel = nt & 1;
                mma16816(acc[mt][nt], ah[cur], bl[bt][sel], bl[bt][sel + 2]);
            }
        }
    }
}

// 2-term split, A hi+lo, B single array (B-hi): computes (Ah+Al)*Bh = A*Bh.
__device__ __forceinline__ void mma_tile_2a(
    float acc[4][4][4], uint32_t sAh, uint32_t sAl, uint32_t sB,
    int wm, int wn, int lane)
{
    int lrow = lane & 15;
    int lcol = (lane >> 4) * 8;
    uint32_t ah[2][4], al[2][4];
    {
        uint32_t off = (uint32_t)(((wm + lrow) * LDAH_ + lcol) * 2);
        ldmx4(ah[0], sAh + off);
        ldmx4(al[0], sAl + off);
    }
#pragma unroll 1
    for (int ks = 0; ks < 8; ++ks) {
        int kk = ks * 16;
        uint32_t bb[2][4];
#pragma unroll
        for (int bt = 0; bt < 2; ++bt) {
            uint32_t off = (uint32_t)(((wn + bt * 16 + lrow) * LDAH_ + kk + lcol) * 2);
            ldmx4(bb[bt], sB + off);
        }
#pragma unroll
        for (int mt = 0; mt < 4; ++mt) {
            int cur = mt & 1, nxt = cur ^ 1;
            if (mt < 3) {
                uint32_t off = (uint32_t)(((wm + (mt + 1) * 16 + lrow) * LDAH_ + kk + lcol) * 2);
                ldmx4(ah[nxt], sAh + off);
                ldmx4(al[nxt], sAl + off);
            } else if (ks < 7) {
                uint32_t off = (uint32_t)(((wm + lrow) * LDAH_ + kk + 16 + lcol) * 2);
                ldmx4(ah[nxt], sAh + off);
                ldmx4(al[nxt], sAl + off);
            }
#pragma unroll
            for (int nt = 0; nt < 4; ++nt) {
                int bt = nt >> 1, sel = nt & 1;
                mma16816(acc[mt][nt], ah[cur], bb[bt][sel], bb[bt][sel + 2]);
            }
#pragma unroll
            for (int nt = 0; nt < 4; ++nt) {
                int bt = nt >> 1, sel = nt & 1;
                mma16816(acc[mt][nt], al[cur], bb[bt][sel], bb[bt][sel + 2]);
            }
        }
    }
}

__device__ __forceinline__ void stage_acc(float* shAcc, float acc[4][4][4],
                                          int wm, int wn, int lane)
{
#pragma unroll
    for (int mt = 0; mt < 4; ++mt)
#pragma unroll
        for (int nt = 0; nt < 4; ++nt) {
            int r = wm + mt * 16 + (lane >> 2);
            int c = wn + nt * 8 + (lane & 3) * 2;
            shAcc[r * 132 + c] = acc[mt][nt][0];
            shAcc[r * 132 + c + 1] = acc[mt][nt][1];
            shAcc[(r + 8) * 132 + c] = acc[mt][nt][2];
            shAcc[(r + 8) * 132 + c + 1] = acc[mt][nt][3];
        }
}

// ---------------------------------------------------------------------------
__global__ void k_prep(const int* __restrict__ ei32) {
    if (blockIdx.x == 0 && threadIdx.x == 0) {
        int all0 = 1;
        for (int i = 0; i < 64; ++i)
            if (ei32[2 * i + 1] != 0) { all0 = 0; break; }
        g_is64 = all0;
    }
    int idx = blockIdx.x * blockDim.x + threadIdx.x;
    float4* p = reinterpret_cast<float4*>(g_agg);
    int n4 = NN_ * HH_ / 4;
    for (int i = idx; i < n4; i += gridDim.x * blockDim.x)
        p[i] = make_float4(0.f, 0.f, 0.f, 0.f);
}

__global__ void k_split_w2(const float* __restrict__ W2) {
    int idx = blockIdx.x * 256 + threadIdx.x;
    int k = idx >> 7, n = idx & 127;
    float v = W2[k * 128 + n];
    __half h = __float2half_rn(v);
    g_W2h[n * 128 + k] = h;
    g_W2l[n * 128 + k] = __float2half_rn(v - __half2float(h));
}

// ---------------------------------------------------------------------------
// K_node: 256 CTAs x 32 rows
__global__ void __launch_bounds__(256)
k_node_enc(const float* __restrict__ x,
           const float* __restrict__ W1, const float* __restrict__ b1,
           const float* __restrict__ a_p,
           const float* __restrict__ W2, const float* __restrict__ b2)
{
    __shared__ float shA[32 * 129];
    __shared__ float shB[32 * 128];
    __shared__ float shX[32 * 33];
    int tid = threadIdx.x;
    int tx = tid & 15, ty = tid >> 4;
    int base = blockIdx.x * 32;

    for (int idx = tid; idx < 32 * 32; idx += 256) {
        int r = idx >> 5, k = idx & 31;
        shX[r * 33 + k] = x[(base + r) * IND_ + k];
    }
    for (int idx = tid; idx < 32 * 128; idx += 256) shB[idx] = W1[idx];
    __syncthreads();

    float acc[2][8];
#pragma unroll
    for (int i = 0; i < 2; ++i)
#pragma unroll
        for (int j = 0; j < 8; ++j) acc[i][j] = 0.f;

#pragma unroll 4
    for (int k = 0; k < 32; ++k) {
        float a0 = shX[(ty * 2 + 0) * 33 + k];
        float a1 = shX[(ty * 2 + 1) * 33 + k];
        float4 b0 = *(const float4*)&shB[k * 128 + tx * 8];
        float4 b1v = *(const float4*)&shB[k * 128 + tx * 8 + 4];
        float bfr[8] = {b0.x, b0.y, b0.z, b0.w, b1v.x, b1v.y, b1v.z, b1v.w};
#pragma unroll
        for (int j = 0; j < 8; ++j) {
            acc[0][j] = fmaf(a0, bfr[j], acc[0][j]);
            acc[1][j] = fmaf(a1, bfr[j], acc[1][j]);
        }
    }
    float a = *a_p;
#pragma unroll
    for (int i = 0; i < 2; ++i)
#pragma unroll
        for (int j = 0; j < 8; ++j) {
            float v = acc[i][j] + b1[tx * 8 + j];
            v = (v >= 0.f) ? v : a * v;
            shA[(ty * 2 + i) * 129 + tx * 8 + j] = v;
            acc[i][j] = 0.f;
        }

    for (int kc = 0; kc < HH_; kc += 32) {
        __syncthreads();
        for (int idx = tid; idx < 32 * 128; idx += 256) shB[idx] = W2[kc * 128 + idx];
        __syncthreads();
#pragma unroll 4
        for (int k = 0; k < 32; ++k) {
            float a0 = shA[(ty * 2 + 0) * 129 + kc + k];
            float a1 = shA[(ty * 2 + 1) * 129 + kc + k];
            float4 b0 = *(const float4*)&shB[k * 128 + tx * 8];
            float4 b1v = *(const float4*)&shB[k * 128 + tx * 8 + 4];
            float bfr[8] = {b0.x, b0.y, b0.z, b0.w, b1v.x, b1v.y, b1v.z, b1v.w};
#pragma unroll
            for (int j = 0; j < 8; ++j) {
                acc[0][j] = fmaf(a0, bfr[j], acc[0][j]);
                acc[1][j] = fmaf(a1, bfr[j], acc[1][j]);
            }
        }
    }
#pragma unroll
    for (int i = 0; i < 2; ++i) {
        int row = base + ty * 2 + i;
#pragma unroll
        for (int j = 0; j < 8; ++j)
            g_cx[row * HH_ + tx * 8 + j] = acc[i][j] + b2[tx * 8 + j];
    }
}

// ---------------------------------------------------------------------------
// K_edge: persistent, producer/consumer, double-buffered A (hi only).
// 2-term split: Ah*(Bh+Bl). smem layout (bytes):
//   A0=0  A1=34816  (h1 hi [128][136] f16, 2 bufs)
//   BH=69632  BL=104448  (W2^T hi/lo [n][k])
//   EA0=139264(2048) EA1=141312
//   SRC0=143360 SRC1=143872 DST0=144384 DST1=144896
//   B2C=145408 (512)   total 145920
__global__ void __launch_bounds__(512, 1)
k_edge(const float* __restrict__ ea, const int* __restrict__ ei32,
       const float* __restrict__ W1, const float* __restrict__ b1,
       const float* __restrict__ a_p, const float* __restrict__ b2,
       int ntiles)
{
    extern __shared__ char smc[];
    float* shB2c = (float*)(smc + 145408);

    int tid = threadIdx.x;
    int lane = tid & 31;
    int is64 = g_is64;
    float a = *a_p;

    {
        const uint4* wh4 = (const uint4*)g_W2h;
        const uint4* wl4 = (const uint4*)g_W2l;
        for (int idx = tid; idx < 2048; idx += 512) {
            int n = idx >> 4, ko = (idx & 15) * 8;
            *(uint4*)(smc + 69632 + (n * LDAH_ + ko) * 2) = wh4[idx];
            *(uint4*)(smc + 104448 + (n * LDAH_ + ko) * 2) = wl4[idx];
        }
        if (tid < 128) shB2c[tid] = b2[tid];
    }

    int iters = (ntiles - blockIdx.x + gridDim.x - 1) / gridDim.x;

    if (tid >= 256) {
        // ---------------- PRODUCER (hi only now) ----------------
        int ptid = tid - 256;
        int jp = (ptid & 63) * 2;
        int eoff = ptid >> 6;
        float w1a[4], w1b[4];
#pragma unroll
        for (int k = 0; k < 4; ++k) {
            w1a[k] = W1[k * 128 + jp];
            w1b[k] = W1[k * 128 + jp + 1];
        }
        float b1a = b1[jp], b1b = b1[jp + 1];

        auto fill = [&](int nb, int t) {
            int e0 = t * 128;
            float* shEA = (float*)(smc + 139264 + nb * 2048);
            int* shSrc = (int*)(smc + 143360 + nb * 512);
            int* shDst = (int*)(smc + 144384 + nb * 512);
            for (int idx = ptid; idx < 512; idx += 256) shEA[idx] = ea[e0 * 4 + idx];
            if (ptid < 128) {
                if (is64) {
                    shSrc[ptid] = ei32[2 * (e0 + ptid)];
                    shDst[ptid] = ei32[2 * (EE_ + e0 + ptid)];
                } else {
                    shSrc[ptid] = ei32[e0 + ptid];
                    shDst[ptid] = ei32[EE_ + e0 + ptid];
                }
            }
            asm volatile("bar.sync 1, 256;" ::: "memory");
            char* pA = smc + nb * 34816;
#pragma unroll 4
            for (int k = 0; k < 32; ++k) {
                int e = eoff + 4 * k;
                float4 er = *(const float4*)&shEA[e * 4];
                float v0 = b1a, v1 = b1b;
                v0 = fmaf(er.x, w1a[0], v0); v1 = fmaf(er.x, w1b[0], v1);
                v0 = fmaf(er.y, w1a[1], v0); v1 = fmaf(er.y, w1b[1], v1);
                v0 = fmaf(er.z, w1a[2], v0); v1 = fmaf(er.z, w1b[2], v1);
                v0 = fmaf(er.w, w1a[3], v0); v1 = fmaf(er.w, w1b[3], v1);
                v0 = (v0 >= 0.f) ? v0 : a * v0;
                v1 = (v1 >= 0.f) ? v1 : a * v1;
                uint32_t hw = __half_as_ushort(__float2half_rn(v0)) |
                              ((uint32_t)__half_as_ushort(__float2half_rn(v1)) << 16);
                *(uint32_t*)(pA + (e * LDAH_ + jp) * 2) = hw;
            }
        };

        fill(0, blockIdx.x);
        __syncthreads();
        for (int i = 0; i < iters; ++i) {
            int nt = i + 1;
            if (nt < iters) fill(nt & 1, blockIdx.x + nt * gridDim.x);
            __syncthreads();
        }
    } else {
        // ---------------- CONSUMER ----------------
        int w = tid >> 5;
        int wm = (w >> 2) * 64, wn = (w & 3) * 32;
        uint32_t sBh = smem_u32(smc + 69632);
        uint32_t sBl = smem_u32(smc + 104448);
        int cc = (lane & 3) * 2;

        __syncthreads();

        float b2v[4][2];
#pragma unroll
        for (int nt = 0; nt < 4; ++nt) {
            int c = wn + nt * 8 + cc;
            b2v[nt][0] = shB2c[c];
            b2v[nt][1] = shB2c[c + 1];
        }

        for (int i = 0; i < iters; ++i) {
            int cb = i & 1;
            uint32_t sA = smem_u32(smc + cb * 34816);
            int* shSrc = (int*)(smc + 143360 + cb * 512);
            int* shDst = (int*)(smc + 144384 + cb * 512);

            float acc[4][4][4] = {};
            mma_tile_2e(acc, sA, sBh, sBl, wm, wn, lane);

            int r0 = lane >> 2;
#pragma unroll
            for (int mt = 0; mt < 4; ++mt) {
                int rA = wm + mt * 16 + r0;
                int rB = rA + 8;
                int sAi = shSrc[rA], dA = shDst[rA];
                int sBi = shSrc[rB], dB = shDst[rB];
#pragma unroll
                for (int nt = 0; nt < 4; ++nt) {
                    int c = wn + nt * 8 + cc;
                    float2 cxA = *(const float2*)&g_cx[sAi * HH_ + c];
                    float2 cxB = *(const float2*)&g_cx[sBi * HH_ + c];
                    float m0 = fmaxf(0.f, acc[mt][nt][0] + b2v[nt][0] + cxA.x);
                    float m1 = fmaxf(0.f, acc[mt][nt][1] + b2v[nt][1] + cxA.y);
                    float m2 = fmaxf(0.f, acc[mt][nt][2] + b2v[nt][0] + cxB.x);
                    float m3 = fmaxf(0.f, acc[mt][nt][3] + b2v[nt][1] + cxB.y);
                    red_add_v2(&g_agg[dA * HH_ + c], m0, m1);
                    red_add_v2(&g_agg[dB * HH_ + c], m2, m3);
                }
            }
            __syncthreads();
        }
    }
}

// ---------------------------------------------------------------------------
// K_mlp: 256 CTAs x 32 rows
__global__ void __launch_bounds__(256)
k_mlp(const float* __restrict__ W1, const float* __restrict__ b1,
      const float* __restrict__ a_p,
      const float* __restrict__ W2, const float* __restrict__ b2,
      const float* __restrict__ eps_p, float* __restrict__ out_z)
{
    __shared__ float shA[32 * 129];
    __shared__ float shB[32 * 128];
    int tid = threadIdx.x;
    int tx = tid & 15, ty = tid >> 4;
    int base = blockIdx.x * 32;

    float ep = 1.0f + *eps_p;
    for (int idx = tid; idx < 32 * 128; idx += 256) {
        int r = idx >> 7, k = idx & 127;
        int g = (base + r) * HH_ + k;
        shA[r * 129 + k] = ep * g_cx[g] + g_agg[g];
    }

    float acc[2][8];
#pragma unroll
    for (int i = 0; i < 2; ++i)
#pragma unroll
        for (int j = 0; j < 8; ++j) acc[i][j] = 0.f;

    for (int kc = 0; kc < HH_; kc += 32) {
        __syncthreads();
        for (int idx = tid; idx < 32 * 128; idx += 256) shB[idx] = W1[kc * 128 + idx];
        __syncthreads();
#pragma unroll 4
        for (int k = 0; k < 32; ++k) {
            float a0 = shA[(ty * 2 + 0) * 129 + kc + k];
            float a1 = shA[(ty * 2 + 1) * 129 + kc + k];
            float4 b0 = *(const float4*)&shB[k * 128 + tx * 8];
            float4 b1v = *(const float4*)&shB[k * 128 + tx * 8 + 4];
            float bfr[8] = {b0.x, b0.y, b0.z, b0.w, b1v.x, b1v.y, b1v.z, b1v.w};
#pragma unroll
            for (int j = 0; j < 8; ++j) {
                acc[0][j] = fmaf(a0, bfr[j], acc[0][j]);
                acc[1][j] = fmaf(a1, bfr[j], acc[1][j]);
            }
        }
    }

    float a = *a_p;
    __syncthreads();
#pragma unroll
    for (int i = 0; i < 2; ++i)
#pragma unroll
        for (int j = 0; j < 8; ++j) {
            float v = acc[i][j] + b1[tx * 8 + j];
            v = (v >= 0.f) ? v : a * v;
            shA[(ty * 2 + i) * 129 + tx * 8 + j] = v;
            acc[i][j] = 0.f;
        }

    for (int kc = 0; kc < HH_; kc += 32) {
        __syncthreads();
        for (int idx = tid; idx < 32 * 128; idx += 256) shB[idx] = W2[kc * 128 + idx];
        __syncthreads();
#pragma unroll 4
        for (int k = 0; k < 32; ++k) {
            float a0 = shA[(ty * 2 + 0) * 129 + kc + k];
            float a1 = shA[(ty * 2 + 1) * 129 + kc + k];
            float4 b0 = *(const float4*)&shB[k * 128 + tx * 8];
            float4 b1v = *(const float4*)&shB[k * 128 + tx * 8 + 4];
            float bfr[8] = {b0.x, b0.y, b0.z, b0.w, b1v.x, b1v.y, b1v.z, b1v.w};
#pragma unroll
            for (int j = 0; j < 8; ++j) {
                acc[0][j] = fmaf(a0, bfr[j], acc[0][j]);
                acc[1][j] = fmaf(a1, bfr[j], acc[1][j]);
            }
        }
    }

#pragma unroll
    for (int i = 0; i < 2; ++i) {
        int row = base + ty * 2 + i;
#pragma unroll
        for (int j = 0; j < 8; ++j) {
            float v = acc[i][j] + b2[tx * 8 + j];
            int g = row * HH_ + tx * 8 + j;
            g_z[g] = v;
            out_z[g] = v;
            __half h = __float2half_rn(v);
            g_zh[g] = h;
            g_zl[g] = __float2half_rn(v - __half2float(h));
        }
    }
}

// ---------------------------------------------------------------------------
__global__ void k_p(const float* __restrict__ pW, const float* __restrict__ pb,
                    float* __restrict__ out_p)
{
    int tid = threadIdx.x;
    int grp = tid >> 4, lane = tid & 15;
    int node = blockIdx.x * 8 + grp;
    const float4* z4 = (const float4*)&g_z[node * HH_];
    float v = pb[lane];
#pragma unroll 8
    for (int k4 = 0; k4 < 32; ++k4) {
        float4 zz = z4[k4];
        int kb = k4 * 4;
        v += zz.x * pW[(kb + 0) * NCC_ + lane];
        v += zz.y * pW[(kb + 1) * NCC_ + lane];
        v += zz.z * pW[(kb + 2) * NCC_ + lane];
        v += zz.w * pW[(kb + 3) * NCC_ + lane];
    }
    float m = v;
#pragma unroll
    for (int off = 8; off > 0; off >>= 1)
        m = fmaxf(m, __shfl_xor_sync(0xffffffffu, m, off, 16));
    float e = expf(v - m);
    float s = e;
#pragma unroll
    for (int off = 8; off > 0; off >>= 1)
        s += __shfl_xor_sync(0xffffffffu, s, off, 16);
    out_p[node * NCC_ + lane] = e / s;
}

// ---------------------------------------------------------------------------
// K_ahat: A_hat = z z^T. 512 threads, 128x256 slab (2 column tiles, shared A).
// 2-term split: (Ah+Al)*Bh. smem: AH=0 AL=34816 B0H=69632 B1H=104448 (139264).
// Staging overlays: group g stages into smc + g*69632 after all MMA complete.
__global__ void __launch_bounds__(512, 1)
k_ahat(float* __restrict__ outA)
{
    int bj2 = blockIdx.x, bi = blockIdx.y;
    int j0 = 2 * bj2, j1 = j0 + 1;
    if (j1 < bi) return;

    extern __shared__ char smc[];
    int tid = threadIdx.x;
    int lane = tid & 31, w = tid >> 5;
    int g = w >> 3, w8 = w & 7;
    int wm = (w8 >> 2) * 64, wn = (w8 & 3) * 32;

    const uint4* zh4 = (const uint4*)g_zh;
    const uint4* zl4 = (const uint4*)g_zl;
    for (int idx = tid; idx < 2048; idx += 512) {
        int r = idx >> 4, kv = idx & 15;
        uint32_t off = (uint32_t)((r * LDAH_ + kv * 8) * 2);
        *(uint4*)(smc + off)          = zh4[(bi * 128 + r) * 16 + kv];
        *(uint4*)(smc + 34816 + off)  = zl4[(bi * 128 + r) * 16 + kv];
        *(uint4*)(smc + 69632 + off)  = zh4[(j0 * 128 + r) * 16 + kv];
        *(uint4*)(smc + 104448 + off) = zh4[(j1 * 128 + r) * 16 + kv];
    }
    __syncthreads();

    int j = j0 + g;
    bool live = (j >= bi);
    float acc[4][4][4] = {};
    if (live)
        mma_tile_2a(acc, smem_u32(smc), smem_u32(smc + 34816),
                    smem_u32(smc + 69632 + g * 34816), wm, wn, lane);
    __syncthreads();

    float* shAcc = (float*)(smc + g * 69632);
    if (live) stage_acc(shAcc, acc, wm, wn, lane);
    __syncthreads();

    int tx = tid & 15, ty = tid >> 4;
    const size_t Ns = NN_;
#pragma unroll
    for (int t = 0; t < 2; ++t) {
        int jt = j0 + t;
        if (jt < bi) continue;
        const float* sa = (const float*)(smc + t * 69632);
#pragma unroll
        for (int i = 0; i < 4; ++i) {
            int r = ty + i * 32;
            const float* row = &sa[r * 132 + tx * 8];
            float4 w0 = make_float4(row[0], row[1], row[2], row[3]);
            float4 w1 = make_float4(row[4], row[5], row[6], row[7]);
            size_t go = (size_t)(bi * 128 + r) * Ns + (size_t)jt * 128 + tx * 8;
            *(float4*)&outA[go] = w0;
            *(float4*)&outA[go + 4] = w1;
        }
        if (jt > bi) {
#pragma unroll
            for (int i = 0; i < 4; ++i) {
                int u = ty + i * 32;
                float4 w0 = make_float4(sa[(tx * 8 + 0) * 132 + u],
                                        sa[(tx * 8 + 1) * 132 + u],
                                        sa[(tx * 8 + 2) * 132 + u],
                                        sa[(tx * 8 + 3) * 132 + u]);
                float4 w1 = make_float4(sa[(tx * 8 + 4) * 132 + u],
                                        sa[(tx * 8 + 5) * 132 + u],
                                        sa[(tx * 8 + 6) * 132 + u],
                                        sa[(tx * 8 + 7) * 132 + u]);
                size_t go = (size_t)(jt * 128 + u) * Ns + (size_t)bi * 128 + tx * 8;
                *(float4*)&outA[go] = w0;
                *(float4*)&outA[go + 4] = w1;
            }
        }
    }
}

// ---------------------------------------------------------------------------
extern "C" void kernel_launch(void* const* d_in, const int* in_sizes, int n_in,
                              void* d_out, int out_size)
{
    const float* x    = (const float*)d_in[0];
    const float* ea   = (const float*)d_in[1];
    const int*   ei32 = (const int*)  d_in[2];
    const float* neW1 = (const float*)d_in[3];
    const float* neb1 = (const float*)d_in[4];
    const float* nea  = (const float*)d_in[5];
    const float* neW2 = (const float*)d_in[6];
    const float* neb2 = (const float*)d_in[7];
    const float* eeW1 = (const float*)d_in[8];
    const float* eeb1 = (const float*)d_in[9];
    const float* eea  = (const float*)d_in[10];
    const float* eeW2 = (const float*)d_in[11];
    const float* eeb2 = (const float*)d_in[12];
    const float* gW1  = (const float*)d_in[13];
    const float* gb1  = (const float*)d_in[14];
    const float* ga   = (const float*)d_in[15];
    const float* gW2  = (const float*)d_in[16];
    const float* gb2  = (const float*)d_in[17];
    const float* eps  = (const float*)d_in[18];
    const float* pW   = (const float*)d_in[19];
    const float* pb   = (const float*)d_in[20];

    float* out   = (float*)d_out;
    float* out_A = out;
    float* out_p = out + (size_t)NN_ * NN_;
    float* out_z = out_p + (size_t)NN_ * NCC_;

    const int smem_edge = 145920;
    const int smem_ahat = 139264;

    cudaFuncSetAttribute(k_edge, cudaFuncAttributeMaxDynamicSharedMemorySize, smem_edge);
    cudaFuncSetAttribute(k_ahat, cudaFuncAttributeMaxDynamicSharedMemorySize, smem_ahat);

    k_prep<<<512, 256>>>(ei32);
    k_node_enc<<<NN_ / 32, 256>>>(x, neW1, neb1, nea, neW2, neb2);
    k_split_w2<<<64, 256>>>(eeW2);
    k_edge<<<148, 512, smem_edge>>>(ea, ei32, eeW1, eeb1, eea, eeb2, EE_ / 128);
    k_mlp<<<NN_ / 32, 256>>>(gW1, gb1, ga, gW2, gb2, eps, out_z);
    k_p<<<NN_ / 8, 128>>>(pW, pb, out_p);
    k_ahat<<<dim3(NN_ / 256, NN_ / 128), 512, smem_ahat>>>(out_A);
}

// round 17
// speedup vs baseline: 1.3619x; 1.1765x over previous
#include <cuda_runtime.h>
#include <cuda_fp16.h>
#include <cstdint>

#define NN_ 8192
#define EE_ 524288
#define HH_ 128
#define IND_ 32
#define NCC_ 16

// Device scratch (static, no allocations)
__device__ __align__(16) float g_cx[NN_ * HH_];
__device__ __align__(16) float g_agg[NN_ * HH_];
__device__ __align__(16) float g_z[NN_ * HH_];
__device__ __align__(16) __half g_zh[NN_ * HH_];
__device__ __align__(16) __half g_W2h[HH_ * HH_];  // eeW2^T [n][k] hi
__device__ int g_is64;

// ---------------------------------------------------------------------------
__device__ __forceinline__ void red_add_v2(float* addr, float x, float y) {
    asm volatile("red.global.add.v2.f32 [%0], {%1,%2};"
                 :: "l"(addr), "f"(x), "f"(y) : "memory");
}
__device__ __forceinline__ uint32_t smem_u32(const void* p) {
    return (uint32_t)__cvta_generic_to_shared(p);
}
__device__ __forceinline__ void ldmx4(uint32_t r[4], uint32_t addr) {
    asm volatile("ldmatrix.sync.aligned.m8n8.x4.shared.b16 {%0,%1,%2,%3}, [%4];"
                 : "=r"(r[0]), "=r"(r[1]), "=r"(r[2]), "=r"(r[3]) : "r"(addr));
}
__device__ __forceinline__ void mma16816(float c[4], const uint32_t a[4],
                                         uint32_t b0, uint32_t b1) {
    asm volatile("mma.sync.aligned.m16n8k16.row.col.f32.f16.f16.f32 "
                 "{%0,%1,%2,%3}, {%4,%5,%6,%7}, {%8,%9}, {%0,%1,%2,%3};"
                 : "+f"(c[0]), "+f"(c[1]), "+f"(c[2]), "+f"(c[3])
                 : "r"(a[0]), "r"(a[1]), "r"(a[2]), "r"(a[3]), "r"(b0), "r"(b1));
}

#define LDAH_ 136
// Single-term fp16 MMA tile: Ah*Bh. 8 warps as 2(m)x4(n), warp tile 64x32,
// reg-pipelined A.
__device__ __forceinline__ void mma_tile_1t(
    float acc[4][4][4], uint32_t sA, uint32_t sB,
    int wm, int wn, int lane)
{
    int lrow = lane & 15;
    int lcol = (lane >> 4) * 8;
    uint32_t ah[2][4];
    {
        uint32_t off = (uint32_t)(((wm + lrow) * LDAH_ + lcol) * 2);
        ldmx4(ah[0], sA + off);
    }
#pragma unroll 1
    for (int ks = 0; ks < 8; ++ks) {
        int kk = ks * 16;
        uint32_t bb[2][4];
#pragma unroll
        for (int bt = 0; bt < 2; ++bt) {
            uint32_t off = (uint32_t)(((wn + bt * 16 + lrow) * LDAH_ + kk + lcol) * 2);
            ldmx4(bb[bt], sB + off);
        }
#pragma unroll
        for (int mt = 0; mt < 4; ++mt) {
            int cur = mt & 1, nxt = cur ^ 1;
            if (mt < 3) {
                uint32_t off = (uint32_t)(((wm + (mt + 1) * 16 + lrow) * LDAH_ + kk + lcol) * 2);
                ldmx4(ah[nxt], sA + off);
            } else if (ks < 7) {
                uint32_t off = (uint32_t)(((wm + lrow) * LDAH_ + kk + 16 + lcol) * 2);
                ldmx4(ah[nxt], sA + off);
            }
#pragma unroll
            for (int nt = 0; nt < 4; ++nt) {
                int bt = nt >> 1, sel = nt & 1;
                mma16816(acc[mt][nt], ah[cur], bb[bt][sel], bb[bt][sel + 2]);
            }
        }
    }
}

__device__ __forceinline__ void stage_acc(float* shAcc, float acc[4][4][4],
                                          int wm, int wn, int lane)
{
#pragma unroll
    for (int mt = 0; mt < 4; ++mt)
#pragma unroll
        for (int nt = 0; nt < 4; ++nt) {
            int r = wm + mt * 16 + (lane >> 2);
            int c = wn + nt * 8 + (lane & 3) * 2;
            shAcc[r * 132 + c] = acc[mt][nt][0];
            shAcc[r * 132 + c + 1] = acc[mt][nt][1];
            shAcc[(r + 8) * 132 + c] = acc[mt][nt][2];
            shAcc[(r + 8) * 132 + c + 1] = acc[mt][nt][3];
        }
}

// ---------------------------------------------------------------------------
__global__ void k_prep(const int* __restrict__ ei32) {
    if (blockIdx.x == 0 && threadIdx.x == 0) {
        int all0 = 1;
        for (int i = 0; i < 64; ++i)
            if (ei32[2 * i + 1] != 0) { all0 = 0; break; }
        g_is64 = all0;
    }
    int idx = blockIdx.x * blockDim.x + threadIdx.x;
    float4* p = reinterpret_cast<float4*>(g_agg);
    int n4 = NN_ * HH_ / 4;
    for (int i = idx; i < n4; i += gridDim.x * blockDim.x)
        p[i] = make_float4(0.f, 0.f, 0.f, 0.f);
}

// eeW2 [k][n] -> transposed fp16 hi [n][k]
__global__ void k_split_w2(const float* __restrict__ W2) {
    int idx = blockIdx.x * 256 + threadIdx.x;
    int k = idx >> 7, n = idx & 127;
    g_W2h[n * 128 + k] = __float2half_rn(W2[k * 128 + n]);
}

// ---------------------------------------------------------------------------
// K_node: 256 CTAs x 32 rows
__global__ void __launch_bounds__(256)
k_node_enc(const float* __restrict__ x,
           const float* __restrict__ W1, const float* __restrict__ b1,
           const float* __restrict__ a_p,
           const float* __restrict__ W2, const float* __restrict__ b2)
{
    __shared__ float shA[32 * 129];
    __shared__ float shB[32 * 128];
    __shared__ float shX[32 * 33];
    int tid = threadIdx.x;
    int tx = tid & 15, ty = tid >> 4;
    int base = blockIdx.x * 32;

    for (int idx = tid; idx < 32 * 32; idx += 256) {
        int r = idx >> 5, k = idx & 31;
        shX[r * 33 + k] = x[(base + r) * IND_ + k];
    }
    for (int idx = tid; idx < 32 * 128; idx += 256) shB[idx] = W1[idx];
    __syncthreads();

    float acc[2][8];
#pragma unroll
    for (int i = 0; i < 2; ++i)
#pragma unroll
        for (int j = 0; j < 8; ++j) acc[i][j] = 0.f;

#pragma unroll 4
    for (int k = 0; k < 32; ++k) {
        float a0 = shX[(ty * 2 + 0) * 33 + k];
        float a1 = shX[(ty * 2 + 1) * 33 + k];
        float4 b0 = *(const float4*)&shB[k * 128 + tx * 8];
        float4 b1v = *(const float4*)&shB[k * 128 + tx * 8 + 4];
        float bfr[8] = {b0.x, b0.y, b0.z, b0.w, b1v.x, b1v.y, b1v.z, b1v.w};
#pragma unroll
        for (int j = 0; j < 8; ++j) {
            acc[0][j] = fmaf(a0, bfr[j], acc[0][j]);
            acc[1][j] = fmaf(a1, bfr[j], acc[1][j]);
        }
    }
    float a = *a_p;
#pragma unroll
    for (int i = 0; i < 2; ++i)
#pragma unroll
        for (int j = 0; j < 8; ++j) {
            float v = acc[i][j] + b1[tx * 8 + j];
            v = (v >= 0.f) ? v : a * v;
            shA[(ty * 2 + i) * 129 + tx * 8 + j] = v;
            acc[i][j] = 0.f;
        }

    for (int kc = 0; kc < HH_; kc += 32) {
        __syncthreads();
        for (int idx = tid; idx < 32 * 128; idx += 256) shB[idx] = W2[kc * 128 + idx];
        __syncthreads();
#pragma unroll 4
        for (int k = 0; k < 32; ++k) {
            float a0 = shA[(ty * 2 + 0) * 129 + kc + k];
            float a1 = shA[(ty * 2 + 1) * 129 + kc + k];
            float4 b0 = *(const float4*)&shB[k * 128 + tx * 8];
            float4 b1v = *(const float4*)&shB[k * 128 + tx * 8 + 4];
            float bfr[8] = {b0.x, b0.y, b0.z, b0.w, b1v.x, b1v.y, b1v.z, b1v.w};
#pragma unroll
            for (int j = 0; j < 8; ++j) {
                acc[0][j] = fmaf(a0, bfr[j], acc[0][j]);
                acc[1][j] = fmaf(a1, bfr[j], acc[1][j]);
            }
        }
    }
#pragma unroll
    for (int i = 0; i < 2; ++i) {
        int row = base + ty * 2 + i;
#pragma unroll
        for (int j = 0; j < 8; ++j)
            g_cx[row * HH_ + tx * 8 + j] = acc[i][j] + b2[tx * 8 + j];
    }
}

// ---------------------------------------------------------------------------
// K_edge: persistent, producer/consumer, double-buffered A (hi only),
// single-term fp16 MMA. smem layout (bytes):
//   A0=0  A1=34816  (h1 hi [128][136] f16, 2 bufs)
//   BH=69632  (W2^T hi [n][k])
//   EA0=104448(2048) EA1=106496
//   SRC0=108544 SRC1=109056 DST0=109568 DST1=110080
//   B2C=110592 (512)   total 111104
__global__ void __launch_bounds__(512, 1)
k_edge(const float* __restrict__ ea, const int* __restrict__ ei32,
       const float* __restrict__ W1, const float* __restrict__ b1,
       const float* __restrict__ a_p, const float* __restrict__ b2,
       int ntiles)
{
    extern __shared__ char smc[];
    float* shB2c = (float*)(smc + 110592);

    int tid = threadIdx.x;
    int lane = tid & 31;
    int is64 = g_is64;
    float a = *a_p;

    {
        const uint4* wh4 = (const uint4*)g_W2h;
        for (int idx = tid; idx < 2048; idx += 512) {
            int n = idx >> 4, ko = (idx & 15) * 8;
            *(uint4*)(smc + 69632 + (n * LDAH_ + ko) * 2) = wh4[idx];
        }
        if (tid < 128) shB2c[tid] = b2[tid];
    }

    int iters = (ntiles - blockIdx.x + gridDim.x - 1) / gridDim.x;

    if (tid >= 256) {
        // ---------------- PRODUCER ----------------
        int ptid = tid - 256;
        int jp = (ptid & 63) * 2;
        int eoff = ptid >> 6;
        float w1a[4], w1b[4];
#pragma unroll
        for (int k = 0; k < 4; ++k) {
            w1a[k] = W1[k * 128 + jp];
            w1b[k] = W1[k * 128 + jp + 1];
        }
        float b1a = b1[jp], b1b = b1[jp + 1];

        auto fill = [&](int nb, int t) {
            int e0 = t * 128;
            float* shEA = (float*)(smc + 104448 + nb * 2048);
            int* shSrc = (int*)(smc + 108544 + nb * 512);
            int* shDst = (int*)(smc + 109568 + nb * 512);
            for (int idx = ptid; idx < 512; idx += 256) shEA[idx] = ea[e0 * 4 + idx];
            if (ptid < 128) {
                if (is64) {
                    shSrc[ptid] = ei32[2 * (e0 + ptid)];
                    shDst[ptid] = ei32[2 * (EE_ + e0 + ptid)];
                } else {
                    shSrc[ptid] = ei32[e0 + ptid];
                    shDst[ptid] = ei32[EE_ + e0 + ptid];
                }
            }
            asm volatile("bar.sync 1, 256;" ::: "memory");
            char* pA = smc + nb * 34816;
#pragma unroll 4
            for (int k = 0; k < 32; ++k) {
                int e = eoff + 4 * k;
                float4 er = *(const float4*)&shEA[e * 4];
                float v0 = b1a, v1 = b1b;
                v0 = fmaf(er.x, w1a[0], v0); v1 = fmaf(er.x, w1b[0], v1);
                v0 = fmaf(er.y, w1a[1], v0); v1 = fmaf(er.y, w1b[1], v1);
                v0 = fmaf(er.z, w1a[2], v0); v1 = fmaf(er.z, w1b[2], v1);
                v0 = fmaf(er.w, w1a[3], v0); v1 = fmaf(er.w, w1b[3], v1);
                v0 = (v0 >= 0.f) ? v0 : a * v0;
                v1 = (v1 >= 0.f) ? v1 : a * v1;
                uint32_t hw = __half_as_ushort(__float2half_rn(v0)) |
                              ((uint32_t)__half_as_ushort(__float2half_rn(v1)) << 16);
                *(uint32_t*)(pA + (e * LDAH_ + jp) * 2) = hw;
            }
        };

        fill(0, blockIdx.x);
        __syncthreads();
        for (int i = 0; i < iters; ++i) {
            int nt = i + 1;
            if (nt < iters) fill(nt & 1, blockIdx.x + nt * gridDim.x);
            __syncthreads();
        }
    } else {
        // ---------------- CONSUMER ----------------
        int w = tid >> 5;
        int wm = (w >> 2) * 64, wn = (w & 3) * 32;
        uint32_t sB = smem_u32(smc + 69632);
        int cc = (lane & 3) * 2;

        __syncthreads();

        float b2v[4][2];
#pragma unroll
        for (int nt = 0; nt < 4; ++nt) {
            int c = wn + nt * 8 + cc;
            b2v[nt][0] = shB2c[c];
            b2v[nt][1] = shB2c[c + 1];
        }

        for (int i = 0; i < iters; ++i) {
            int cb = i & 1;
            uint32_t sA = smem_u32(smc + cb * 34816);
            int* shSrc = (int*)(smc + 108544 + cb * 512);
            int* shDst = (int*)(smc + 109568 + cb * 512);

            float acc[4][4][4] = {};
            mma_tile_1t(acc, sA, sB, wm, wn, lane);

            int r0 = lane >> 2;
#pragma unroll
            for (int mt = 0; mt < 4; ++mt) {
                int rA = wm + mt * 16 + r0;
                int rB = rA + 8;
                int sAi = shSrc[rA], dA = shDst[rA];
                int sBi = shSrc[rB], dB = shDst[rB];
#pragma unroll
                for (int nt = 0; nt < 4; ++nt) {
                    int c = wn + nt * 8 + cc;
                    float2 cxA = *(const float2*)&g_cx[sAi * HH_ + c];
                    float2 cxB = *(const float2*)&g_cx[sBi * HH_ + c];
                    float m0 = fmaxf(0.f, acc[mt][nt][0] + b2v[nt][0] + cxA.x);
                    float m1 = fmaxf(0.f, acc[mt][nt][1] + b2v[nt][1] + cxA.y);
                    float m2 = fmaxf(0.f, acc[mt][nt][2] + b2v[nt][0] + cxB.x);
                    float m3 = fmaxf(0.f, acc[mt][nt][3] + b2v[nt][1] + cxB.y);
                    red_add_v2(&g_agg[dA * HH_ + c], m0, m1);
                    red_add_v2(&g_agg[dB * HH_ + c], m2, m3);
                }
            }
            __syncthreads();
        }
    }
}

// ---------------------------------------------------------------------------
// K_mlp: 256 CTAs x 32 rows. Stores z fp32 + z-hi fp16 (no lo needed).
__global__ void __launch_bounds__(256)
k_mlp(const float* __restrict__ W1, const float* __restrict__ b1,
      const float* __restrict__ a_p,
      const float* __restrict__ W2, const float* __restrict__ b2,
      const float* __restrict__ eps_p, float* __restrict__ out_z)
{
    __shared__ float shA[32 * 129];
    __shared__ float shB[32 * 128];
    int tid = threadIdx.x;
    int tx = tid & 15, ty = tid >> 4;
    int base = blockIdx.x * 32;

    float ep = 1.0f + *eps_p;
    for (int idx = tid; idx < 32 * 128; idx += 256) {
        int r = idx >> 7, k = idx & 127;
        int g = (base + r) * HH_ + k;
        shA[r * 129 + k] = ep * g_cx[g] + g_agg[g];
    }

    float acc[2][8];
#pragma unroll
    for (int i = 0; i < 2; ++i)
#pragma unroll
        for (int j = 0; j < 8; ++j) acc[i][j] = 0.f;

    for (int kc = 0; kc < HH_; kc += 32) {
        __syncthreads();
        for (int idx = tid; idx < 32 * 128; idx += 256) shB[idx] = W1[kc * 128 + idx];
        __syncthreads();
#pragma unroll 4
        for (int k = 0; k < 32; ++k) {
            float a0 = shA[(ty * 2 + 0) * 129 + kc + k];
            float a1 = shA[(ty * 2 + 1) * 129 + kc + k];
            float4 b0 = *(const float4*)&shB[k * 128 + tx * 8];
            float4 b1v = *(const float4*)&shB[k * 128 + tx * 8 + 4];
            float bfr[8] = {b0.x, b0.y, b0.z, b0.w, b1v.x, b1v.y, b1v.z, b1v.w};
#pragma unroll
            for (int j = 0; j < 8; ++j) {
                acc[0][j] = fmaf(a0, bfr[j], acc[0][j]);
                acc[1][j] = fmaf(a1, bfr[j], acc[1][j]);
            }
        }
    }

    float a = *a_p;
    __syncthreads();
#pragma unroll
    for (int i = 0; i < 2; ++i)
#pragma unroll
        for (int j = 0; j < 8; ++j) {
            float v = acc[i][j] + b1[tx * 8 + j];
            v = (v >= 0.f) ? v : a * v;
            shA[(ty * 2 + i) * 129 + tx * 8 + j] = v;
            acc[i][j] = 0.f;
        }

    for (int kc = 0; kc < HH_; kc += 32) {
        __syncthreads();
        for (int idx = tid; idx < 32 * 128; idx += 256) shB[idx] = W2[kc * 128 + idx];
        __syncthreads();
#pragma unroll 4
        for (int k = 0; k < 32; ++k) {
            float a0 = shA[(ty * 2 + 0) * 129 + kc + k];
            float a1 = shA[(ty * 2 + 1) * 129 + kc + k];
            float4 b0 = *(const float4*)&shB[k * 128 + tx * 8];
            float4 b1v = *(const float4*)&shB[k * 128 + tx * 8 + 4];
            float bfr[8] = {b0.x, b0.y, b0.z, b0.w, b1v.x, b1v.y, b1v.z, b1v.w};
#pragma unroll
            for (int j = 0; j < 8; ++j) {
                acc[0][j] = fmaf(a0, bfr[j], acc[0][j]);
                acc[1][j] = fmaf(a1, bfr[j], acc[1][j]);
            }
        }
    }

#pragma unroll
    for (int i = 0; i < 2; ++i) {
        int row = base + ty * 2 + i;
#pragma unroll
        for (int j = 0; j < 8; ++j) {
            float v = acc[i][j] + b2[tx * 8 + j];
            int g = row * HH_ + tx * 8 + j;
            g_z[g] = v;
            out_z[g] = v;
            g_zh[g] = __float2half_rn(v);
        }
    }
}

// ---------------------------------------------------------------------------
__global__ void k_p(const float* __restrict__ pW, const float* __restrict__ pb,
                    float* __restrict__ out_p)
{
    int tid = threadIdx.x;
    int grp = tid >> 4, lane = tid & 15;
    int node = blockIdx.x * 8 + grp;
    const float4* z4 = (const float4*)&g_z[node * HH_];
    float v = pb[lane];
#pragma unroll 8
    for (int k4 = 0; k4 < 32; ++k4) {
        float4 zz = z4[k4];
        int kb = k4 * 4;
        v += zz.x * pW[(kb + 0) * NCC_ + lane];
        v += zz.y * pW[(kb + 1) * NCC_ + lane];
        v += zz.z * pW[(kb + 2) * NCC_ + lane];
        v += zz.w * pW[(kb + 3) * NCC_ + lane];
    }
    float m = v;
#pragma unroll
    for (int off = 8; off > 0; off >>= 1)
        m = fmaxf(m, __shfl_xor_sync(0xffffffffu, m, off, 16));
    float e = expf(v - m);
    float s = e;
#pragma unroll
    for (int off = 8; off > 0; off >>= 1)
        s += __shfl_xor_sync(0xffffffffu, s, off, 16);
    out_p[node * NCC_ + lane] = e / s;
}

// ---------------------------------------------------------------------------
// K_ahat: A_hat = z z^T. 512 threads, 128x256 slab, single-term fp16.
// smem: AH=0 B0H=34816 B1H=69632 (104448 operands).
// Staging: group g overlays smc + g*67584 ([0,135168)). smem total 135168.
__global__ void __launch_bounds__(512, 1)
k_ahat(float* __restrict__ outA)
{
    int bj2 = blockIdx.x, bi = blockIdx.y;
    int j0 = 2 * bj2, j1 = j0 + 1;
    if (j1 < bi) return;

    extern __shared__ char smc[];
    int tid = threadIdx.x;
    int lane = tid & 31, w = tid >> 5;
    int g = w >> 3, w8 = w & 7;
    int wm = (w8 >> 2) * 64, wn = (w8 & 3) * 32;

    const uint4* zh4 = (const uint4*)g_zh;
    for (int idx = tid; idx < 2048; idx += 512) {
        int r = idx >> 4, kv = idx & 15;
        uint32_t off = (uint32_t)((r * LDAH_ + kv * 8) * 2);
        *(uint4*)(smc + off)         = zh4[(bi * 128 + r) * 16 + kv];
        *(uint4*)(smc + 34816 + off) = zh4[(j0 * 128 + r) * 16 + kv];
        *(uint4*)(smc + 69632 + off) = zh4[(j1 * 128 + r) * 16 + kv];
    }
    __syncthreads();

    int j = j0 + g;
    bool live = (j >= bi);
    float acc[4][4][4] = {};
    if (live)
        mma_tile_1t(acc, smem_u32(smc), smem_u32(smc + 34816 + g * 34816),
                    wm, wn, lane);
    __syncthreads();

    float* shAcc = (float*)(smc + g * 67584);
    if (live) stage_acc(shAcc, acc, wm, wn, lane);
    __syncthreads();

    int tx = tid & 15, ty = tid >> 4;
    const size_t Ns = NN_;
#pragma unroll
    for (int t = 0; t < 2; ++t) {
        int jt = j0 + t;
        if (jt < bi) continue;
        const float* sa = (const float*)(smc + t * 67584);
#pragma unroll
        for (int i = 0; i < 4; ++i) {
            int r = ty + i * 32;
            const float* row = &sa[r * 132 + tx * 8];
            float4 w0 = make_float4(row[0], row[1], row[2], row[3]);
            float4 w1 = make_float4(row[4], row[5], row[6], row[7]);
            size_t go = (size_t)(bi * 128 + r) * Ns + (size_t)jt * 128 + tx * 8;
            *(float4*)&outA[go] = w0;
            *(float4*)&outA[go + 4] = w1;
        }
        if (jt > bi) {
#pragma unroll
            for (int i = 0; i < 4; ++i) {
                int u = ty + i * 32;
                float4 w0 = make_float4(sa[(tx * 8 + 0) * 132 + u],
                                        sa[(tx * 8 + 1) * 132 + u],
                                        sa[(tx * 8 + 2) * 132 + u],
                                        sa[(tx * 8 + 3) * 132 + u]);
                float4 w1 = make_float4(sa[(tx * 8 + 4) * 132 + u],
                                        sa[(tx * 8 + 5) * 132 + u],
                                        sa[(tx * 8 + 6) * 132 + u],
                                        sa[(tx * 8 + 7) * 132 + u]);
                size_t go = (size_t)(jt * 128 + u) * Ns + (size_t)bi * 128 + tx * 8;
                *(float4*)&outA[go] = w0;
                *(float4*)&outA[go + 4] = w1;
            }
        }
    }
}

// ---------------------------------------------------------------------------
extern "C" void kernel_launch(void* const* d_in, const int* in_sizes, int n_in,
                              void* d_out, int out_size)
{
    const float* x    = (const float*)d_in[0];
    const float* ea   = (const float*)d_in[1];
    const int*   ei32 = (const int*)  d_in[2];
    const float* neW1 = (const float*)d_in[3];
    const float* neb1 = (const float*)d_in[4];
    const float* nea  = (const float*)d_in[5];
    const float* neW2 = (const float*)d_in[6];
    const float* neb2 = (const float*)d_in[7];
    const float* eeW1 = (const float*)d_in[8];
    const float* eeb1 = (const float*)d_in[9];
    const float* eea  = (const float*)d_in[10];
    const float* eeW2 = (const float*)d_in[11];
    const float* eeb2 = (const float*)d_in[12];
    const float* gW1  = (const float*)d_in[13];
    const float* gb1  = (const float*)d_in[14];
    const float* ga   = (const float*)d_in[15];
    const float* gW2  = (const float*)d_in[16];
    const float* gb2  = (const float*)d_in[17];
    const float* eps  = (const float*)d_in[18];
    const float* pW   = (const float*)d_in[19];
    const float* pb   = (const float*)d_in[20];

    float* out   = (float*)d_out;
    float* out_A = out;
    float* out_p = out + (size_t)NN_ * NN_;
    float* out_z = out_p + (size_t)NN_ * NCC_;

    const int smem_edge = 111104;
    const int smem_ahat = 135168;

    cudaFuncSetAttribute(k_edge, cudaFuncAttributeMaxDynamicSharedMemorySize, smem_edge);
    cudaFuncSetAttribute(k_ahat, cudaFuncAttributeMaxDynamicSharedMemorySize, smem_ahat);

    k_prep<<<512, 256>>>(ei32);
    k_node_enc<<<NN_ / 32, 256>>>(x, neW1, neb1, nea, neW2, neb2);
    k_split_w2<<<64, 256>>>(eeW2);
    k_edge<<<148, 512, smem_edge>>>(ea, ei32, eeW1, eeb1, eea, eeb2, EE_ / 128);
    k_mlp<<<NN_ / 32, 256>>>(gW1, gb1, ga, gW2, gb2, eps, out_z);
    k_p<<<NN_ / 8, 128>>>(pW, pb, out_p);
    k_ahat<<<dim3(NN_ / 256, NN_ / 128), 512, smem_ahat>>>(out_A);
}